// round 3
// baseline (speedup 1.0000x reference)
#include <cuda_runtime.h>
#include <math.h>
#include <stdint.h>

// Problem constants
#define T_DIM    4096
#define HIDDEN   2048
#define N_HEADS  16
#define N_KV     4
#define HEAD_DIM 128
#define WINDOW   1024
#define QKV_OUT  3072           // (16 + 2*4) * 128
#define Q_SIZE   2048           // 16*128
#define KV_SIZE  512            // 4*128

// Scratch (no cudaMalloc allowed)
__device__ float g_qkv [(size_t)T_DIM * QKV_OUT];            // 50.3 MB
__device__ float g_attn[(size_t)T_DIM * N_HEADS * HEAD_DIM]; // 33.5 MB

// ---------------------------------------------------------------------------
// SGEMM: C[M,N] = A[M,K] @ B[K,N] (+ bias[N]) ; row-major, dims divisible
// 128x128 block, BK=16, 256 threads, 8x8 microtile, double-buffered smem
// ---------------------------------------------------------------------------
#define BM 128
#define BN 128
#define BK 16

__global__ __launch_bounds__(256) void sgemm_kernel(
    const float* __restrict__ A, const float* __restrict__ B,
    const float* __restrict__ bias, float* __restrict__ C,
    int M, int N, int K)
{
    __shared__ float As[2][BK][BM];
    __shared__ float Bs[2][BK][BN];

    const int tid = threadIdx.x;
    const int tx  = tid & 15;        // 0..15
    const int ty  = tid >> 4;        // 0..15
    const int m0  = blockIdx.y * BM;
    const int n0  = blockIdx.x * BN;

    float acc[8][8];
#pragma unroll
    for (int i = 0; i < 8; i++)
#pragma unroll
        for (int j = 0; j < 8; j++) acc[i][j] = 0.f;

    // A tile: 128 rows x 16 cols; thread: row tid>>1, cols (tid&1)*8 .. +7
    const int arow = tid >> 1;           // 0..127
    const int acol = (tid & 1) * 8;      // 0 or 8
    // B tile: 16 rows x 128 cols; thread: row tid>>4, cols (tid&15)*8 .. +7
    const int brow = tid >> 4;           // 0..15
    const int bcol = (tid & 15) * 8;     // 0..120

    const float* Ap = A + (size_t)(m0 + arow) * K + acol;
    const float* Bp = B + (size_t)brow * N + n0 + bcol;

    // Preload tile 0 into buffer 0
    {
        float4 av0 = *(const float4*)(Ap + 0);
        float4 av1 = *(const float4*)(Ap + 4);
        float4 bv0 = *(const float4*)(Bp + 0);
        float4 bv1 = *(const float4*)(Bp + 4);
        As[0][acol + 0][arow] = av0.x;
        As[0][acol + 1][arow] = av0.y;
        As[0][acol + 2][arow] = av0.z;
        As[0][acol + 3][arow] = av0.w;
        As[0][acol + 4][arow] = av1.x;
        As[0][acol + 5][arow] = av1.y;
        As[0][acol + 6][arow] = av1.z;
        As[0][acol + 7][arow] = av1.w;
        *(float4*)&Bs[0][brow][bcol + 0] = bv0;
        *(float4*)&Bs[0][brow][bcol + 4] = bv1;
    }
    __syncthreads();

    int cur = 0;
    for (int k0 = 0; k0 < K; k0 += BK) {
        const bool has_next = (k0 + BK) < K;
        float4 av0, av1, bv0, bv1;
        if (has_next) {
            av0 = *(const float4*)(Ap + BK + 0);
            av1 = *(const float4*)(Ap + BK + 4);
            bv0 = *(const float4*)(Bp + (size_t)BK * N + 0);
            bv1 = *(const float4*)(Bp + (size_t)BK * N + 4);
        }

#pragma unroll
        for (int kk = 0; kk < BK; kk++) {
            float a[8], b[8];
            *(float4*)&a[0] = *(const float4*)&As[cur][kk][ty * 8];
            *(float4*)&a[4] = *(const float4*)&As[cur][kk][ty * 8 + 4];
            *(float4*)&b[0] = *(const float4*)&Bs[cur][kk][tx * 8];
            *(float4*)&b[4] = *(const float4*)&Bs[cur][kk][tx * 8 + 4];
#pragma unroll
            for (int i = 0; i < 8; i++)
#pragma unroll
                for (int j = 0; j < 8; j++)
                    acc[i][j] += a[i] * b[j];
        }

        if (has_next) {
            const int nxt = cur ^ 1;
            As[nxt][acol + 0][arow] = av0.x;
            As[nxt][acol + 1][arow] = av0.y;
            As[nxt][acol + 2][arow] = av0.z;
            As[nxt][acol + 3][arow] = av0.w;
            As[nxt][acol + 4][arow] = av1.x;
            As[nxt][acol + 5][arow] = av1.y;
            As[nxt][acol + 6][arow] = av1.z;
            As[nxt][acol + 7][arow] = av1.w;
            *(float4*)&Bs[nxt][brow][bcol + 0] = bv0;
            *(float4*)&Bs[nxt][brow][bcol + 4] = bv1;
            __syncthreads();
            cur = nxt;
        }
        Ap += BK;
        Bp += (size_t)BK * N;
    }

    float bvals[8];
#pragma unroll
    for (int j = 0; j < 8; j++)
        bvals[j] = bias ? bias[n0 + tx * 8 + j] : 0.f;

#pragma unroll
    for (int i = 0; i < 8; i++) {
        float* Crow = C + (size_t)(m0 + ty * 8 + i) * N + n0 + tx * 8;
        float4 v0 = make_float4(acc[i][0] + bvals[0], acc[i][1] + bvals[1],
                                acc[i][2] + bvals[2], acc[i][3] + bvals[3]);
        float4 v1 = make_float4(acc[i][4] + bvals[4], acc[i][5] + bvals[5],
                                acc[i][6] + bvals[6], acc[i][7] + bvals[7]);
        ((float4*)Crow)[0] = v0;
        ((float4*)Crow)[1] = v1;
    }
}

// ---------------------------------------------------------------------------
// RoPE: in-place on q (16 heads) and k (4 heads) sections of g_qkv
// grid (T, 20), 64 threads; thread d handles pair (d, d+64)
// ---------------------------------------------------------------------------
__global__ void rope_kernel(const int* __restrict__ positions)
{
    const int t  = blockIdx.x;
    const int hh = blockIdx.y;            // 0..15 = q heads, 16..19 = k heads
    const int d  = threadIdx.x;           // 0..63

    const size_t base = (size_t)t * QKV_OUT +
        ((hh < N_HEADS) ? hh * HEAD_DIM : Q_SIZE + (hh - N_HEADS) * HEAD_DIM);

    const float pos = (float)positions[t];
    const float inv_freq = powf(100000.0f, -((float)d) * (1.0f / 64.0f));
    float sn, cs;
    sincosf(pos * inv_freq, &sn, &cs);

    const float x1 = g_qkv[base + d];
    const float x2 = g_qkv[base + d + 64];
    g_qkv[base + d]      = x1 * cs - x2 * sn;
    g_qkv[base + d + 64] = x2 * cs + x1 * sn;
}

// ---------------------------------------------------------------------------
// Flash attention with sliding window + GQA
// Block: 64 queries x 1 head, 256 threads (8 warps).
// Warp w owns 8 rows; lane (ry,cx) = (lane/8, lane%8) owns rows {8w+ry, 8w+ry+4},
// score cols {cx+8j}, output dims [16*cx, 16*cx+16).
// ---------------------------------------------------------------------------
#define AQ 64
#define AK 64
#define QS_STRIDE 132   // 128 + 4 pad (float4-aligned, conflict-free col reads)
#define P_STRIDE  65

#define ATTN_SMEM_FLOATS (3 * AQ * QS_STRIDE + AQ * P_STRIDE)
#define ATTN_SMEM_BYTES  (ATTN_SMEM_FLOATS * 4)

__global__ __launch_bounds__(256) void attn_kernel()
{
    extern __shared__ float sm[];
    float* Qs = sm;                         // 64 x 132
    float* Ks = Qs + AQ * QS_STRIDE;        // 64 x 132
    float* Vs = Ks + AQ * QS_STRIDE;        // 64 x 132
    float* Ps = Vs + AQ * QS_STRIDE;        // 64 x 65

    const int tid = threadIdx.x;
    const int h   = blockIdx.y;
    const int qb  = blockIdx.x * AQ;
    const int kvh = h >> 2;                 // group = 4

    // Load Q tile (coalesced float4)
#pragma unroll
    for (int it = 0; it < 8; it++) {
        int idx = it * 256 + tid;           // 0..2047
        int r   = idx >> 5;
        int c4  = idx & 31;
        float4 v = *(const float4*)&g_qkv[(size_t)(qb + r) * QKV_OUT + h * HEAD_DIM + c4 * 4];
        *(float4*)&Qs[r * QS_STRIDE + c4 * 4] = v;
    }

    const int warp = tid >> 5;
    const int lane = tid & 31;
    const int ry = lane >> 3;
    const int cx = lane & 7;
    const int r0 = warp * 8 + ry;
    const int r1 = r0 + 4;
    const int i0 = qb + r0;
    const int i1 = qb + r1;

    float m0 = -1e30f, m1 = -1e30f, l0 = 0.f, l1 = 0.f;
    float o0[16], o1[16];
#pragma unroll
    for (int u = 0; u < 16; u++) { o0[u] = 0.f; o1[u] = 0.f; }

    int lo = qb - WINDOW;
    if (lo < 0) lo = 0;                     // qb, WINDOW multiples of 64
    const float scale = 0.08838834764831845f;  // 1/sqrt(128)

    for (int kt = lo; kt <= qb; kt += AK) {
        __syncthreads();
        // Load K and V tiles
#pragma unroll
        for (int it = 0; it < 8; it++) {
            int idx = it * 256 + tid;
            int r   = idx >> 5;
            int c4  = idx & 31;
            size_t base = (size_t)(kt + r) * QKV_OUT;
            *(float4*)&Ks[r * QS_STRIDE + c4 * 4] =
                *(const float4*)&g_qkv[base + Q_SIZE + kvh * HEAD_DIM + c4 * 4];
            *(float4*)&Vs[r * QS_STRIDE + c4 * 4] =
                *(const float4*)&g_qkv[base + Q_SIZE + KV_SIZE + kvh * HEAD_DIM + c4 * 4];
        }
        __syncthreads();

        // S = Q @ K^T for the lane's 2 rows x 8 cols
        float s0[8], s1[8];
#pragma unroll
        for (int jj = 0; jj < 8; jj++) { s0[jj] = 0.f; s1[jj] = 0.f; }

        const float4* q0p = (const float4*)&Qs[r0 * QS_STRIDE];
        const float4* q1p = (const float4*)&Qs[r1 * QS_STRIDE];
#pragma unroll 4
        for (int d4 = 0; d4 < 32; d4++) {
            float4 q0 = q0p[d4];
            float4 q1 = q1p[d4];
#pragma unroll
            for (int jj = 0; jj < 8; jj++) {
                float4 kv = *(const float4*)&Ks[(cx + 8 * jj) * QS_STRIDE + d4 * 4];
                s0[jj] += q0.x * kv.x + q0.y * kv.y + q0.z * kv.z + q0.w * kv.w;
                s1[jj] += q1.x * kv.x + q1.y * kv.y + q1.z * kv.z + q1.w * kv.w;
            }
        }

        // Scale + sliding-window causal mask
        float rm0 = -1e30f, rm1 = -1e30f;
#pragma unroll
        for (int jj = 0; jj < 8; jj++) {
            int j = kt + cx + 8 * jj;
            s0[jj] = (j <= i0 && j >= i0 - WINDOW) ? s0[jj] * scale : -INFINITY;
            s1[jj] = (j <= i1 && j >= i1 - WINDOW) ? s1[jj] * scale : -INFINITY;
            rm0 = fmaxf(rm0, s0[jj]);
            rm1 = fmaxf(rm1, s1[jj]);
        }
#pragma unroll
        for (int off = 1; off < 8; off <<= 1) {
            rm0 = fmaxf(rm0, __shfl_xor_sync(0xffffffffu, rm0, off));
            rm1 = fmaxf(rm1, __shfl_xor_sync(0xffffffffu, rm1, off));
        }

        float mn0 = fmaxf(m0, rm0), mn1 = fmaxf(m1, rm1);
        float c0 = __expf(m0 - mn0), c1 = __expf(m1 - mn1);
        float rs0 = 0.f, rs1 = 0.f;
#pragma unroll
        for (int jj = 0; jj < 8; jj++) {
            float p0 = __expf(s0[jj] - mn0);
            float p1 = __expf(s1[jj] - mn1);
            Ps[r0 * P_STRIDE + cx + 8 * jj] = p0;
            Ps[r1 * P_STRIDE + cx + 8 * jj] = p1;
            rs0 += p0;
            rs1 += p1;
        }
#pragma unroll
        for (int off = 1; off < 8; off <<= 1) {
            rs0 += __shfl_xor_sync(0xffffffffu, rs0, off);
            rs1 += __shfl_xor_sync(0xffffffffu, rs1, off);
        }
        l0 = l0 * c0 + rs0;
        l1 = l1 * c1 + rs1;
        m0 = mn0;
        m1 = mn1;
#pragma unroll
        for (int u = 0; u < 16; u++) { o0[u] *= c0; o1[u] *= c1; }

        __syncwarp();

        // O += P @ V  (lane's dims: [16*cx, 16*cx+16))
#pragma unroll 4
        for (int k = 0; k < AK; k++) {
            float p0 = Ps[r0 * P_STRIDE + k];
            float p1 = Ps[r1 * P_STRIDE + k];
            const float4* vp = (const float4*)&Vs[k * QS_STRIDE + cx * 16];
#pragma unroll
            for (int u = 0; u < 4; u++) {
                float4 vv = vp[u];
                o0[u * 4 + 0] += p0 * vv.x;
                o0[u * 4 + 1] += p0 * vv.y;
                o0[u * 4 + 2] += p0 * vv.z;
                o0[u * 4 + 3] += p0 * vv.w;
                o1[u * 4 + 0] += p1 * vv.x;
                o1[u * 4 + 1] += p1 * vv.y;
                o1[u * 4 + 2] += p1 * vv.z;
                o1[u * 4 + 3] += p1 * vv.w;
            }
        }
    }

    const float inv0 = 1.f / l0;
    const float inv1 = 1.f / l1;
    float* out0 = &g_attn[(size_t)i0 * (N_HEADS * HEAD_DIM) + h * HEAD_DIM + cx * 16];
    float* out1 = &g_attn[(size_t)i1 * (N_HEADS * HEAD_DIM) + h * HEAD_DIM + cx * 16];
#pragma unroll
    for (int u = 0; u < 4; u++) {
        ((float4*)out0)[u] = make_float4(o0[u * 4 + 0] * inv0, o0[u * 4 + 1] * inv0,
                                         o0[u * 4 + 2] * inv0, o0[u * 4 + 3] * inv0);
        ((float4*)out1)[u] = make_float4(o1[u * 4 + 0] * inv1, o1[u * 4 + 1] * inv1,
                                         o1[u * 4 + 2] * inv1, o1[u * 4 + 3] * inv1);
    }
}

// ---------------------------------------------------------------------------
// Launch
// ---------------------------------------------------------------------------
extern "C" void kernel_launch(void* const* d_in, const int* in_sizes, int n_in,
                              void* d_out, int out_size)
{
    const float* hidden    = (const float*)d_in[0];
    const int*   positions = (const int*)  d_in[1];
    const float* w_qkv     = (const float*)d_in[2];
    const float* b_qkv     = (const float*)d_in[3];
    const float* w_o       = (const float*)d_in[4];
    float*       out       = (float*)d_out;

    float* qkv_ptr  = nullptr;
    float* attn_ptr = nullptr;
    cudaGetSymbolAddress((void**)&qkv_ptr,  g_qkv);
    cudaGetSymbolAddress((void**)&attn_ptr, g_attn);

    cudaFuncSetAttribute(attn_kernel,
                         cudaFuncAttributeMaxDynamicSharedMemorySize,
                         ATTN_SMEM_BYTES);

    // 1) QKV projection + bias
    sgemm_kernel<<<dim3(QKV_OUT / BN, T_DIM / BM), 256>>>(
        hidden, w_qkv, b_qkv, qkv_ptr, T_DIM, QKV_OUT, HIDDEN);

    // 2) RoPE on q + k heads
    rope_kernel<<<dim3(T_DIM, N_HEADS + N_KV), 64>>>(positions);

    // 3) Sliding-window GQA flash attention
    attn_kernel<<<dim3(T_DIM / AQ, N_HEADS), 256, ATTN_SMEM_BYTES>>>();

    // 4) Output projection
    sgemm_kernel<<<dim3(HIDDEN / BN, T_DIM / BM), 256>>>(
        attn_ptr, w_o, nullptr, out, T_DIM, HIDDEN, N_HEADS * HEAD_DIM);
}

// round 4
// speedup vs baseline: 1.3265x; 1.3265x over previous
#include <cuda_runtime.h>
#include <math.h>
#include <stdint.h>

// Problem constants
#define T_DIM    4096
#define HIDDEN   2048
#define N_HEADS  16
#define N_KV     4
#define HEAD_DIM 128
#define WINDOW   1024
#define QKV_OUT  3072           // (16 + 2*4) * 128
#define Q_SIZE   2048           // 16*128
#define KV_SIZE  512            // 4*128

// Scratch (no cudaMalloc allowed)
__device__ float g_qkv [(size_t)T_DIM * QKV_OUT];            // 50.3 MB
__device__ float g_attn[(size_t)T_DIM * N_HEADS * HEAD_DIM]; // 33.5 MB

// ---------------------------------------------------------------------------
// TF32 tensor-core GEMM: C[M,N] = A[M,K] @ B[K,N] (+ bias[N])
// 128x128 block, BK=16, 256 threads (8 warps in 2x4), warp tile 64x32,
// mma.sync.m16n8k8.tf32, double-buffered smem.
// ---------------------------------------------------------------------------
#define BM 128
#define BN 128
#define BK 16
#define AS_STRIDE 20    // BK + 4: conflict-free A fragment reads
#define BS_STRIDE 129   // BN + 1

__device__ __forceinline__ uint32_t f2tf32(float x) {
    uint32_t u;
    asm("cvt.rna.tf32.f32 %0, %1;" : "=r"(u) : "f"(x));
    return u;
}

__device__ __forceinline__ void mma_tf32(
    float& c0, float& c1, float& c2, float& c3,
    uint32_t a0, uint32_t a1, uint32_t a2, uint32_t a3,
    uint32_t b0, uint32_t b1)
{
    asm("mma.sync.aligned.m16n8k8.row.col.f32.tf32.tf32.f32 "
        "{%0,%1,%2,%3}, {%4,%5,%6,%7}, {%8,%9}, {%0,%1,%2,%3};"
        : "+f"(c0), "+f"(c1), "+f"(c2), "+f"(c3)
        : "r"(a0), "r"(a1), "r"(a2), "r"(a3), "r"(b0), "r"(b1));
}

__global__ __launch_bounds__(256) void gemm_tf32_kernel(
    const float* __restrict__ A, const float* __restrict__ B,
    const float* __restrict__ bias, float* __restrict__ C,
    int M, int N, int K)
{
    __shared__ uint32_t As[2][BM][AS_STRIDE];   // [row][k], tf32 bits
    __shared__ uint32_t Bs[2][BK][BS_STRIDE];   // [k][col], tf32 bits

    const int tid = threadIdx.x;
    const int m0  = blockIdx.y * BM;
    const int n0  = blockIdx.x * BN;

    const int wid  = tid >> 5;
    const int lane = tid & 31;
    const int wm   = wid >> 2;        // 0..1
    const int wn   = wid & 3;         // 0..3
    const int g    = lane >> 2;       // 0..7
    const int t    = lane & 3;        // 0..3

    float c[4][4][4];                 // [mtile][ntile][frag]
#pragma unroll
    for (int i = 0; i < 4; i++)
#pragma unroll
        for (int j = 0; j < 4; j++)
#pragma unroll
            for (int u = 0; u < 4; u++) c[i][j][u] = 0.f;

    // Global-load mapping (same as before)
    const int arow = tid >> 1;          // 0..127
    const int acol = (tid & 1) * 8;     // 0 or 8
    const int brow = tid >> 4;          // 0..15
    const int bcol = (tid & 15) * 8;    // 0..120

    const float* Ap = A + (size_t)(m0 + arow) * K + acol;
    const float* Bp = B + (size_t)brow * N + n0 + bcol;

    // Preload tile 0 into buffer 0
    {
        float4 av0 = *(const float4*)(Ap + 0);
        float4 av1 = *(const float4*)(Ap + 4);
        float4 bv0 = *(const float4*)(Bp + 0);
        float4 bv1 = *(const float4*)(Bp + 4);
        uint4 ua0 = make_uint4(f2tf32(av0.x), f2tf32(av0.y), f2tf32(av0.z), f2tf32(av0.w));
        uint4 ua1 = make_uint4(f2tf32(av1.x), f2tf32(av1.y), f2tf32(av1.z), f2tf32(av1.w));
        *(uint4*)&As[0][arow][acol + 0] = ua0;
        *(uint4*)&As[0][arow][acol + 4] = ua1;
        Bs[0][brow][bcol + 0] = f2tf32(bv0.x);
        Bs[0][brow][bcol + 1] = f2tf32(bv0.y);
        Bs[0][brow][bcol + 2] = f2tf32(bv0.z);
        Bs[0][brow][bcol + 3] = f2tf32(bv0.w);
        Bs[0][brow][bcol + 4] = f2tf32(bv1.x);
        Bs[0][brow][bcol + 5] = f2tf32(bv1.y);
        Bs[0][brow][bcol + 6] = f2tf32(bv1.z);
        Bs[0][brow][bcol + 7] = f2tf32(bv1.w);
    }
    __syncthreads();

    int cur = 0;
    for (int k0 = 0; k0 < K; k0 += BK) {
        const bool has_next = (k0 + BK) < K;
        float4 av0, av1, bv0, bv1;
        if (has_next) {
            av0 = *(const float4*)(Ap + BK + 0);
            av1 = *(const float4*)(Ap + BK + 4);
            bv0 = *(const float4*)(Bp + (size_t)BK * N + 0);
            bv1 = *(const float4*)(Bp + (size_t)BK * N + 4);
        }

        // Compute on current buffer: 2 k-steps of 8
#pragma unroll
        for (int ks = 0; ks < 2; ks++) {
            const int kk = ks * 8;
            uint32_t bf0[4], bf1[4];
#pragma unroll
            for (int nt = 0; nt < 4; nt++) {
                const int col = wn * 32 + nt * 8 + g;
                bf0[nt] = Bs[cur][kk + t][col];
                bf1[nt] = Bs[cur][kk + 4 + t][col];
            }
#pragma unroll
            for (int mt = 0; mt < 4; mt++) {
                const int r = wm * 64 + mt * 16 + g;
                uint32_t a0 = As[cur][r][kk + t];
                uint32_t a1 = As[cur][r + 8][kk + t];
                uint32_t a2 = As[cur][r][kk + t + 4];
                uint32_t a3 = As[cur][r + 8][kk + t + 4];
#pragma unroll
                for (int nt = 0; nt < 4; nt++)
                    mma_tf32(c[mt][nt][0], c[mt][nt][1], c[mt][nt][2], c[mt][nt][3],
                             a0, a1, a2, a3, bf0[nt], bf1[nt]);
            }
        }

        if (has_next) {
            const int nxt = cur ^ 1;
            uint4 ua0 = make_uint4(f2tf32(av0.x), f2tf32(av0.y), f2tf32(av0.z), f2tf32(av0.w));
            uint4 ua1 = make_uint4(f2tf32(av1.x), f2tf32(av1.y), f2tf32(av1.z), f2tf32(av1.w));
            *(uint4*)&As[nxt][arow][acol + 0] = ua0;
            *(uint4*)&As[nxt][arow][acol + 4] = ua1;
            Bs[nxt][brow][bcol + 0] = f2tf32(bv0.x);
            Bs[nxt][brow][bcol + 1] = f2tf32(bv0.y);
            Bs[nxt][brow][bcol + 2] = f2tf32(bv0.z);
            Bs[nxt][brow][bcol + 3] = f2tf32(bv0.w);
            Bs[nxt][brow][bcol + 4] = f2tf32(bv1.x);
            Bs[nxt][brow][bcol + 5] = f2tf32(bv1.y);
            Bs[nxt][brow][bcol + 6] = f2tf32(bv1.z);
            Bs[nxt][brow][bcol + 7] = f2tf32(bv1.w);
            __syncthreads();
            cur = nxt;
        }
        Ap += BK;
        Bp += (size_t)BK * N;
    }

    // Epilogue: c0 @ (row g, col 2t), c1 col+1, c2 row+8, c3 row+8 col+1
#pragma unroll
    for (int mt = 0; mt < 4; mt++) {
#pragma unroll
        for (int nt = 0; nt < 4; nt++) {
            const int row0 = m0 + wm * 64 + mt * 16 + g;
            const int row1 = row0 + 8;
            const int col  = n0 + wn * 32 + nt * 8 + 2 * t;
            float bb0 = bias ? bias[col]     : 0.f;
            float bb1 = bias ? bias[col + 1] : 0.f;
            float2 v0 = make_float2(c[mt][nt][0] + bb0, c[mt][nt][1] + bb1);
            float2 v1 = make_float2(c[mt][nt][2] + bb0, c[mt][nt][3] + bb1);
            *(float2*)&C[(size_t)row0 * N + col] = v0;
            *(float2*)&C[(size_t)row1 * N + col] = v1;
        }
    }
}

// ---------------------------------------------------------------------------
// RoPE: in-place on q (16 heads) and k (4 heads) sections of g_qkv
// ---------------------------------------------------------------------------
__global__ void rope_kernel(const int* __restrict__ positions)
{
    const int t  = blockIdx.x;
    const int hh = blockIdx.y;            // 0..15 = q heads, 16..19 = k heads
    const int d  = threadIdx.x;           // 0..63

    const size_t base = (size_t)t * QKV_OUT +
        ((hh < N_HEADS) ? hh * HEAD_DIM : Q_SIZE + (hh - N_HEADS) * HEAD_DIM);

    const float pos = (float)positions[t];
    const float inv_freq = powf(100000.0f, -((float)d) * (1.0f / 64.0f));
    float sn, cs;
    sincosf(pos * inv_freq, &sn, &cs);

    const float x1 = g_qkv[base + d];
    const float x2 = g_qkv[base + d + 64];
    g_qkv[base + d]      = x1 * cs - x2 * sn;
    g_qkv[base + d + 64] = x2 * cs + x1 * sn;
}

// ---------------------------------------------------------------------------
// Flash attention with sliding window + GQA (unchanged from passing R3)
// ---------------------------------------------------------------------------
#define AQ 64
#define AK 64
#define QS_STRIDE 132
#define P_STRIDE  65

#define ATTN_SMEM_FLOATS (3 * AQ * QS_STRIDE + AQ * P_STRIDE)
#define ATTN_SMEM_BYTES  (ATTN_SMEM_FLOATS * 4)

__global__ __launch_bounds__(256) void attn_kernel()
{
    extern __shared__ float sm[];
    float* Qs = sm;                         // 64 x 132
    float* Ks = Qs + AQ * QS_STRIDE;        // 64 x 132
    float* Vs = Ks + AQ * QS_STRIDE;        // 64 x 132
    float* Ps = Vs + AQ * QS_STRIDE;        // 64 x 65

    const int tid = threadIdx.x;
    const int h   = blockIdx.y;
    const int qb  = blockIdx.x * AQ;
    const int kvh = h >> 2;

#pragma unroll
    for (int it = 0; it < 8; it++) {
        int idx = it * 256 + tid;
        int r   = idx >> 5;
        int c4  = idx & 31;
        float4 v = *(const float4*)&g_qkv[(size_t)(qb + r) * QKV_OUT + h * HEAD_DIM + c4 * 4];
        *(float4*)&Qs[r * QS_STRIDE + c4 * 4] = v;
    }

    const int warp = tid >> 5;
    const int lane = tid & 31;
    const int ry = lane >> 3;
    const int cx = lane & 7;
    const int r0 = warp * 8 + ry;
    const int r1 = r0 + 4;
    const int i0 = qb + r0;
    const int i1 = qb + r1;

    float m0 = -1e30f, m1 = -1e30f, l0 = 0.f, l1 = 0.f;
    float o0[16], o1[16];
#pragma unroll
    for (int u = 0; u < 16; u++) { o0[u] = 0.f; o1[u] = 0.f; }

    int lo = qb - WINDOW;
    if (lo < 0) lo = 0;
    const float scale = 0.08838834764831845f;

    for (int kt = lo; kt <= qb; kt += AK) {
        __syncthreads();
#pragma unroll
        for (int it = 0; it < 8; it++) {
            int idx = it * 256 + tid;
            int r   = idx >> 5;
            int c4  = idx & 31;
            size_t base = (size_t)(kt + r) * QKV_OUT;
            *(float4*)&Ks[r * QS_STRIDE + c4 * 4] =
                *(const float4*)&g_qkv[base + Q_SIZE + kvh * HEAD_DIM + c4 * 4];
            *(float4*)&Vs[r * QS_STRIDE + c4 * 4] =
                *(const float4*)&g_qkv[base + Q_SIZE + KV_SIZE + kvh * HEAD_DIM + c4 * 4];
        }
        __syncthreads();

        float s0[8], s1[8];
#pragma unroll
        for (int jj = 0; jj < 8; jj++) { s0[jj] = 0.f; s1[jj] = 0.f; }

        const float4* q0p = (const float4*)&Qs[r0 * QS_STRIDE];
        const float4* q1p = (const float4*)&Qs[r1 * QS_STRIDE];
#pragma unroll 4
        for (int d4 = 0; d4 < 32; d4++) {
            float4 q0 = q0p[d4];
            float4 q1 = q1p[d4];
#pragma unroll
            for (int jj = 0; jj < 8; jj++) {
                float4 kv = *(const float4*)&Ks[(cx + 8 * jj) * QS_STRIDE + d4 * 4];
                s0[jj] += q0.x * kv.x + q0.y * kv.y + q0.z * kv.z + q0.w * kv.w;
                s1[jj] += q1.x * kv.x + q1.y * kv.y + q1.z * kv.z + q1.w * kv.w;
            }
        }

        float rm0 = -1e30f, rm1 = -1e30f;
#pragma unroll
        for (int jj = 0; jj < 8; jj++) {
            int j = kt + cx + 8 * jj;
            s0[jj] = (j <= i0 && j >= i0 - WINDOW) ? s0[jj] * scale : -INFINITY;
            s1[jj] = (j <= i1 && j >= i1 - WINDOW) ? s1[jj] * scale : -INFINITY;
            rm0 = fmaxf(rm0, s0[jj]);
            rm1 = fmaxf(rm1, s1[jj]);
        }
#pragma unroll
        for (int off = 1; off < 8; off <<= 1) {
            rm0 = fmaxf(rm0, __shfl_xor_sync(0xffffffffu, rm0, off));
            rm1 = fmaxf(rm1, __shfl_xor_sync(0xffffffffu, rm1, off));
        }

        float mn0 = fmaxf(m0, rm0), mn1 = fmaxf(m1, rm1);
        float c0 = __expf(m0 - mn0), c1 = __expf(m1 - mn1);
        float rs0 = 0.f, rs1 = 0.f;
#pragma unroll
        for (int jj = 0; jj < 8; jj++) {
            float p0 = __expf(s0[jj] - mn0);
            float p1 = __expf(s1[jj] - mn1);
            Ps[r0 * P_STRIDE + cx + 8 * jj] = p0;
            Ps[r1 * P_STRIDE + cx + 8 * jj] = p1;
            rs0 += p0;
            rs1 += p1;
        }
#pragma unroll
        for (int off = 1; off < 8; off <<= 1) {
            rs0 += __shfl_xor_sync(0xffffffffu, rs0, off);
            rs1 += __shfl_xor_sync(0xffffffffu, rs1, off);
        }
        l0 = l0 * c0 + rs0;
        l1 = l1 * c1 + rs1;
        m0 = mn0;
        m1 = mn1;
#pragma unroll
        for (int u = 0; u < 16; u++) { o0[u] *= c0; o1[u] *= c1; }

        __syncwarp();

#pragma unroll 4
        for (int k = 0; k < AK; k++) {
            float p0 = Ps[r0 * P_STRIDE + k];
            float p1 = Ps[r1 * P_STRIDE + k];
            const float4* vp = (const float4*)&Vs[k * QS_STRIDE + cx * 16];
#pragma unroll
            for (int u = 0; u < 4; u++) {
                float4 vv = vp[u];
                o0[u * 4 + 0] += p0 * vv.x;
                o0[u * 4 + 1] += p0 * vv.y;
                o0[u * 4 + 2] += p0 * vv.z;
                o0[u * 4 + 3] += p0 * vv.w;
                o1[u * 4 + 0] += p1 * vv.x;
                o1[u * 4 + 1] += p1 * vv.y;
                o1[u * 4 + 2] += p1 * vv.z;
                o1[u * 4 + 3] += p1 * vv.w;
            }
        }
    }

    const float inv0 = 1.f / l0;
    const float inv1 = 1.f / l1;
    float* out0 = &g_attn[(size_t)i0 * (N_HEADS * HEAD_DIM) + h * HEAD_DIM + cx * 16];
    float* out1 = &g_attn[(size_t)i1 * (N_HEADS * HEAD_DIM) + h * HEAD_DIM + cx * 16];
#pragma unroll
    for (int u = 0; u < 4; u++) {
        ((float4*)out0)[u] = make_float4(o0[u * 4 + 0] * inv0, o0[u * 4 + 1] * inv0,
                                         o0[u * 4 + 2] * inv0, o0[u * 4 + 3] * inv0);
        ((float4*)out1)[u] = make_float4(o1[u * 4 + 0] * inv1, o1[u * 4 + 1] * inv1,
                                         o1[u * 4 + 2] * inv1, o1[u * 4 + 3] * inv1);
    }
}

// ---------------------------------------------------------------------------
// Launch
// ---------------------------------------------------------------------------
extern "C" void kernel_launch(void* const* d_in, const int* in_sizes, int n_in,
                              void* d_out, int out_size)
{
    const float* hidden    = (const float*)d_in[0];
    const int*   positions = (const int*)  d_in[1];
    const float* w_qkv     = (const float*)d_in[2];
    const float* b_qkv     = (const float*)d_in[3];
    const float* w_o       = (const float*)d_in[4];
    float*       out       = (float*)d_out;

    float* qkv_ptr  = nullptr;
    float* attn_ptr = nullptr;
    cudaGetSymbolAddress((void**)&qkv_ptr,  g_qkv);
    cudaGetSymbolAddress((void**)&attn_ptr, g_attn);

    cudaFuncSetAttribute(attn_kernel,
                         cudaFuncAttributeMaxDynamicSharedMemorySize,
                         ATTN_SMEM_BYTES);

    // 1) QKV projection + bias (TF32 tensor cores)
    gemm_tf32_kernel<<<dim3(QKV_OUT / BN, T_DIM / BM), 256>>>(
        hidden, w_qkv, b_qkv, qkv_ptr, T_DIM, QKV_OUT, HIDDEN);

    // 2) RoPE on q + k heads
    rope_kernel<<<dim3(T_DIM, N_HEADS + N_KV), 64>>>(positions);

    // 3) Sliding-window GQA flash attention
    attn_kernel<<<dim3(T_DIM / AQ, N_HEADS), 256, ATTN_SMEM_BYTES>>>();

    // 4) Output projection (TF32 tensor cores)
    gemm_tf32_kernel<<<dim3(HIDDEN / BN, T_DIM / BM), 256>>>(
        attn_ptr, w_o, nullptr, out, T_DIM, HIDDEN, N_HEADS * HEAD_DIM);
}

// round 7
// speedup vs baseline: 2.0373x; 1.5359x over previous
#include <cuda_runtime.h>
#include <math.h>
#include <stdint.h>

// Problem constants
#define T_DIM    4096
#define HIDDEN   2048
#define N_HEADS  16
#define N_KV     4
#define HEAD_DIM 128
#define WINDOW   1024
#define QKV_OUT  3072           // (16 + 2*4) * 128
#define Q_SIZE   2048           // 16*128
#define KV_SIZE  512            // 4*128

// Scratch (no cudaMalloc allowed)
__device__ float g_qkv [(size_t)T_DIM * QKV_OUT];            // 50.3 MB
__device__ float g_attn[(size_t)T_DIM * N_HEADS * HEAD_DIM]; // 33.5 MB

__device__ __forceinline__ uint32_t f2tf32(float x) {
    uint32_t u;
    asm("cvt.rna.tf32.f32 %0, %1;" : "=r"(u) : "f"(x));
    return u;
}

__device__ __forceinline__ void mma_tf32(
    float& c0, float& c1, float& c2, float& c3,
    uint32_t a0, uint32_t a1, uint32_t a2, uint32_t a3,
    uint32_t b0, uint32_t b1)
{
    asm("mma.sync.aligned.m16n8k8.row.col.f32.tf32.tf32.f32 "
        "{%0,%1,%2,%3}, {%4,%5,%6,%7}, {%8,%9}, {%0,%1,%2,%3};"
        : "+f"(c0), "+f"(c1), "+f"(c2), "+f"(c3)
        : "r"(a0), "r"(a1), "r"(a2), "r"(a3), "r"(b0), "r"(b1));
}

// ---------------------------------------------------------------------------
// TF32 tensor-core GEMM: C[M,N] = A[M,K] @ B[K,N] (+ bias[N])
// 128x128 block, BK=16, 256 threads (8 warps in 2x4), warp tile 64x32
// ---------------------------------------------------------------------------
#define BM 128
#define BN 128
#define BK 16
#define AS_STRIDE 20    // BK + 4: conflict-free A fragment reads
#define BS_STRIDE 129   // BN + 1

__global__ __launch_bounds__(256) void gemm_tf32_kernel(
    const float* __restrict__ A, const float* __restrict__ B,
    const float* __restrict__ bias, float* __restrict__ C,
    int M, int N, int K)
{
    __shared__ uint32_t As[2][BM][AS_STRIDE];   // [row][k], tf32 bits
    __shared__ uint32_t Bs[2][BK][BS_STRIDE];   // [k][col], tf32 bits

    const int tid = threadIdx.x;
    const int m0  = blockIdx.y * BM;
    const int n0  = blockIdx.x * BN;

    const int wid  = tid >> 5;
    const int lane = tid & 31;
    const int wm   = wid >> 2;        // 0..1
    const int wn   = wid & 3;         // 0..3
    const int g    = lane >> 2;       // 0..7
    const int t    = lane & 3;        // 0..3

    float c[4][4][4];
#pragma unroll
    for (int i = 0; i < 4; i++)
#pragma unroll
        for (int j = 0; j < 4; j++)
#pragma unroll
            for (int u = 0; u < 4; u++) c[i][j][u] = 0.f;

    const int arow = tid >> 1;
    const int acol = (tid & 1) * 8;
    const int brow = tid >> 4;
    const int bcol = (tid & 15) * 8;

    const float* Ap = A + (size_t)(m0 + arow) * K + acol;
    const float* Bp = B + (size_t)brow * N + n0 + bcol;

    {
        float4 av0 = *(const float4*)(Ap + 0);
        float4 av1 = *(const float4*)(Ap + 4);
        float4 bv0 = *(const float4*)(Bp + 0);
        float4 bv1 = *(const float4*)(Bp + 4);
        uint4 ua0 = make_uint4(f2tf32(av0.x), f2tf32(av0.y), f2tf32(av0.z), f2tf32(av0.w));
        uint4 ua1 = make_uint4(f2tf32(av1.x), f2tf32(av1.y), f2tf32(av1.z), f2tf32(av1.w));
        *(uint4*)&As[0][arow][acol + 0] = ua0;
        *(uint4*)&As[0][arow][acol + 4] = ua1;
        Bs[0][brow][bcol + 0] = f2tf32(bv0.x);
        Bs[0][brow][bcol + 1] = f2tf32(bv0.y);
        Bs[0][brow][bcol + 2] = f2tf32(bv0.z);
        Bs[0][brow][bcol + 3] = f2tf32(bv0.w);
        Bs[0][brow][bcol + 4] = f2tf32(bv1.x);
        Bs[0][brow][bcol + 5] = f2tf32(bv1.y);
        Bs[0][brow][bcol + 6] = f2tf32(bv1.z);
        Bs[0][brow][bcol + 7] = f2tf32(bv1.w);
    }
    __syncthreads();

    int cur = 0;
    for (int k0 = 0; k0 < K; k0 += BK) {
        const bool has_next = (k0 + BK) < K;
        float4 av0, av1, bv0, bv1;
        if (has_next) {
            av0 = *(const float4*)(Ap + BK + 0);
            av1 = *(const float4*)(Ap + BK + 4);
            bv0 = *(const float4*)(Bp + (size_t)BK * N + 0);
            bv1 = *(const float4*)(Bp + (size_t)BK * N + 4);
        }

#pragma unroll
        for (int ks = 0; ks < 2; ks++) {
            const int kk = ks * 8;
            uint32_t bf0[4], bf1[4];
#pragma unroll
            for (int nt = 0; nt < 4; nt++) {
                const int col = wn * 32 + nt * 8 + g;
                bf0[nt] = Bs[cur][kk + t][col];
                bf1[nt] = Bs[cur][kk + 4 + t][col];
            }
#pragma unroll
            for (int mt = 0; mt < 4; mt++) {
                const int r = wm * 64 + mt * 16 + g;
                uint32_t a0 = As[cur][r][kk + t];
                uint32_t a1 = As[cur][r + 8][kk + t];
                uint32_t a2 = As[cur][r][kk + t + 4];
                uint32_t a3 = As[cur][r + 8][kk + t + 4];
#pragma unroll
                for (int nt = 0; nt < 4; nt++)
                    mma_tf32(c[mt][nt][0], c[mt][nt][1], c[mt][nt][2], c[mt][nt][3],
                             a0, a1, a2, a3, bf0[nt], bf1[nt]);
            }
        }

        if (has_next) {
            const int nxt = cur ^ 1;
            uint4 ua0 = make_uint4(f2tf32(av0.x), f2tf32(av0.y), f2tf32(av0.z), f2tf32(av0.w));
            uint4 ua1 = make_uint4(f2tf32(av1.x), f2tf32(av1.y), f2tf32(av1.z), f2tf32(av1.w));
            *(uint4*)&As[nxt][arow][acol + 0] = ua0;
            *(uint4*)&As[nxt][arow][acol + 4] = ua1;
            Bs[nxt][brow][bcol + 0] = f2tf32(bv0.x);
            Bs[nxt][brow][bcol + 1] = f2tf32(bv0.y);
            Bs[nxt][brow][bcol + 2] = f2tf32(bv0.z);
            Bs[nxt][brow][bcol + 3] = f2tf32(bv0.w);
            Bs[nxt][brow][bcol + 4] = f2tf32(bv1.x);
            Bs[nxt][brow][bcol + 5] = f2tf32(bv1.y);
            Bs[nxt][brow][bcol + 6] = f2tf32(bv1.z);
            Bs[nxt][brow][bcol + 7] = f2tf32(bv1.w);
            __syncthreads();
            cur = nxt;
        }
        Ap += BK;
        Bp += (size_t)BK * N;
    }

#pragma unroll
    for (int mt = 0; mt < 4; mt++) {
#pragma unroll
        for (int nt = 0; nt < 4; nt++) {
            const int row0 = m0 + wm * 64 + mt * 16 + g;
            const int row1 = row0 + 8;
            const int col  = n0 + wn * 32 + nt * 8 + 2 * t;
            float bb0 = bias ? bias[col]     : 0.f;
            float bb1 = bias ? bias[col + 1] : 0.f;
            float2 v0 = make_float2(c[mt][nt][0] + bb0, c[mt][nt][1] + bb1);
            float2 v1 = make_float2(c[mt][nt][2] + bb0, c[mt][nt][3] + bb1);
            *(float2*)&C[(size_t)row0 * N + col] = v0;
            *(float2*)&C[(size_t)row1 * N + col] = v1;
        }
    }
}

// ---------------------------------------------------------------------------
// RoPE: in-place on q (16 heads) and k (4 heads) sections of g_qkv
// ---------------------------------------------------------------------------
__global__ void rope_kernel(const int* __restrict__ positions)
{
    const int t  = blockIdx.x;
    const int hh = blockIdx.y;
    const int d  = threadIdx.x;

    const size_t base = (size_t)t * QKV_OUT +
        ((hh < N_HEADS) ? hh * HEAD_DIM : Q_SIZE + (hh - N_HEADS) * HEAD_DIM);

    const float pos = (float)positions[t];
    const float inv_freq = powf(100000.0f, -((float)d) * (1.0f / 64.0f));
    float sn, cs;
    sincosf(pos * inv_freq, &sn, &cs);

    const float x1 = g_qkv[base + d];
    const float x2 = g_qkv[base + d + 64];
    g_qkv[base + d]      = x1 * cs - x2 * sn;
    g_qkv[base + d + 64] = x2 * cs + x1 * sn;
}

// ---------------------------------------------------------------------------
// Flash attention: QK^T on tf32 tensor cores, PV fp32 SIMT.
// Block: 64 queries x 1 head, 128 threads (4 warps). Warp w owns rows
// [16w, 16w+16) as one m16 mma slab; Q fragments in registers.
// ---------------------------------------------------------------------------
#define AQ 64
#define AK 64
#define KS_STRIDE 132   // uint32 words; banks 4g+t conflict-free
#define VS_STRIDE 132
#define P_STRIDE  66

// smem: Ks (tf32) + Vs (f32) + Ps (f32) + crow + lrow
#define ATTN_SMEM_BYTES ((AK * KS_STRIDE + AK * VS_STRIDE + AQ * P_STRIDE + 2 * AQ) * 4)

__global__ __launch_bounds__(128, 2) void attn_kernel()
{
    extern __shared__ uint32_t smraw[];
    uint32_t* Ks  = smraw;                          // 64 x 132 tf32 bits
    float*    Vs  = (float*)(Ks + AK * KS_STRIDE);  // 64 x 132 f32
    float*    Ps  = Vs + AK * VS_STRIDE;            // 64 x 66  f32
    float*    crow = Ps + AQ * P_STRIDE;            // 64
    float*    lrow = crow + AQ;                     // 64

    const int tid  = threadIdx.x;
    const int h    = blockIdx.y;
    const int qb   = blockIdx.x * AQ;
    const int kvh  = h >> 2;

    const int warp = tid >> 5;
    const int lane = tid & 31;
    const int g    = lane >> 2;        // 0..7
    const int t    = lane & 3;         // 0..3

    // mma row indices
    const int i0 = qb + warp * 16 + g;
    const int i1 = i0 + 8;

    // Q fragments in registers: 16 k-steps x 4 regs (tf32)
    uint32_t qa[16][4];
    {
        const float* q0p = &g_qkv[(size_t)i0 * QKV_OUT + h * HEAD_DIM];
        const float* q1p = q0p + (size_t)8 * QKV_OUT;
#pragma unroll
        for (int ks = 0; ks < 16; ks++) {
            qa[ks][0] = f2tf32(q0p[8 * ks + t]);
            qa[ks][1] = f2tf32(q1p[8 * ks + t]);
            qa[ks][2] = f2tf32(q0p[8 * ks + t + 4]);
            qa[ks][3] = f2tf32(q1p[8 * ks + t + 4]);
        }
    }

    // SIMT PV mapping: thread owns rows {rr+16u} (u=0..3), dims [16cx,16cx+16)
    const int rr = tid >> 3;           // 0..15
    const int cx = tid & 7;            // 0..7
    float o[4][16];
#pragma unroll
    for (int u = 0; u < 4; u++)
#pragma unroll
        for (int d = 0; d < 16; d++) o[u][d] = 0.f;

    float m0 = -1e30f, m1 = -1e30f, l0 = 0.f, l1 = 0.f;

    int lo = qb - WINDOW;
    if (lo < 0) lo = 0;
    const float scale = 0.08838834764831845f;

    for (int kt = lo; kt <= qb; kt += AK) {
        __syncthreads();
        // Load K (tf32-converted) and V tiles: 64 rows x 32 float4 each
#pragma unroll
        for (int it = 0; it < 16; it++) {
            int idx = it * 128 + tid;       // 0..2047
            int r   = idx >> 5;
            int c4  = idx & 31;
            size_t base = (size_t)(kt + r) * QKV_OUT + Q_SIZE + kvh * HEAD_DIM + c4 * 4;
            float4 kv = *(const float4*)&g_qkv[base];
            float4 vv = *(const float4*)&g_qkv[base + KV_SIZE];
            uint4 uk = make_uint4(f2tf32(kv.x), f2tf32(kv.y), f2tf32(kv.z), f2tf32(kv.w));
            *(uint4*)&Ks[r * KS_STRIDE + c4 * 4] = uk;
            *(float4*)&Vs[r * VS_STRIDE + c4 * 4] = vv;
        }
        __syncthreads();

        // ---- S = Q @ K^T via tensor cores: 8 n-tiles x 16 k-steps ----
        float s[8][4];
#pragma unroll
        for (int nt = 0; nt < 8; nt++)
#pragma unroll
            for (int u = 0; u < 4; u++) s[nt][u] = 0.f;

#pragma unroll
        for (int ks = 0; ks < 16; ks++) {
#pragma unroll
            for (int nt = 0; nt < 8; nt++) {
                uint32_t b0 = Ks[(8 * nt + g) * KS_STRIDE + 8 * ks + t];
                uint32_t b1 = Ks[(8 * nt + g) * KS_STRIDE + 8 * ks + t + 4];
                mma_tf32(s[nt][0], s[nt][1], s[nt][2], s[nt][3],
                         qa[ks][0], qa[ks][1], qa[ks][2], qa[ks][3], b0, b1);
            }
        }

        // ---- mask + scale + fragment softmax ----
        float rm0 = -INFINITY, rm1 = -INFINITY;
#pragma unroll
        for (int nt = 0; nt < 8; nt++) {
#pragma unroll
            for (int e = 0; e < 2; e++) {
                int j = kt + nt * 8 + 2 * t + e;
                bool v0 = (j <= i0) && (j + WINDOW >= i0);
                bool v1 = (j <= i1) && (j + WINDOW >= i1);
                s[nt][e]     = v0 ? s[nt][e]     * scale : -INFINITY;
                s[nt][2 + e] = v1 ? s[nt][2 + e] * scale : -INFINITY;
                rm0 = fmaxf(rm0, s[nt][e]);
                rm1 = fmaxf(rm1, s[nt][2 + e]);
            }
        }
        // reduce over the 4-lane t-quad (lanes g*4 + {0..3})
        rm0 = fmaxf(rm0, __shfl_xor_sync(0xffffffffu, rm0, 1));
        rm0 = fmaxf(rm0, __shfl_xor_sync(0xffffffffu, rm0, 2));
        rm1 = fmaxf(rm1, __shfl_xor_sync(0xffffffffu, rm1, 1));
        rm1 = fmaxf(rm1, __shfl_xor_sync(0xffffffffu, rm1, 2));

        float mn0 = fmaxf(m0, rm0), mn1 = fmaxf(m1, rm1);
        float c0 = __expf(m0 - mn0), c1 = __expf(m1 - mn1);
        float rs0 = 0.f, rs1 = 0.f;
#pragma unroll
        for (int nt = 0; nt < 8; nt++) {
            float p00 = __expf(s[nt][0] - mn0);
            float p01 = __expf(s[nt][1] - mn0);
            float p10 = __expf(s[nt][2] - mn1);
            float p11 = __expf(s[nt][3] - mn1);
            *(float2*)&Ps[(warp * 16 + g) * P_STRIDE + nt * 8 + 2 * t] = make_float2(p00, p01);
            *(float2*)&Ps[(warp * 16 + g + 8) * P_STRIDE + nt * 8 + 2 * t] = make_float2(p10, p11);
            rs0 += p00 + p01;
            rs1 += p10 + p11;
        }
        rs0 += __shfl_xor_sync(0xffffffffu, rs0, 1);
        rs0 += __shfl_xor_sync(0xffffffffu, rs0, 2);
        rs1 += __shfl_xor_sync(0xffffffffu, rs1, 1);
        rs1 += __shfl_xor_sync(0xffffffffu, rs1, 2);

        l0 = l0 * c0 + rs0;
        l1 = l1 * c1 + rs1;
        m0 = mn0;
        m1 = mn1;
        if (t == 0) {
            crow[warp * 16 + g]     = c0;
            crow[warp * 16 + g + 8] = c1;
        }
        __syncthreads();   // Ps + crow visible to all

        // ---- O = O*c + P @ V (fp32 SIMT) ----
        float cr[4];
#pragma unroll
        for (int u = 0; u < 4; u++) cr[u] = crow[rr + 16 * u];
#pragma unroll
        for (int u = 0; u < 4; u++)
#pragma unroll
            for (int d = 0; d < 16; d++) o[u][d] *= cr[u];

#pragma unroll 2
        for (int k = 0; k < AK; k++) {
            const float4* vp = (const float4*)&Vs[k * VS_STRIDE + cx * 16];
            float4 v0 = vp[0], v1 = vp[1], v2 = vp[2], v3 = vp[3];
#pragma unroll
            for (int u = 0; u < 4; u++) {
                float p = Ps[(rr + 16 * u) * P_STRIDE + k];
                o[u][0]  += p * v0.x;  o[u][1]  += p * v0.y;
                o[u][2]  += p * v0.z;  o[u][3]  += p * v0.w;
                o[u][4]  += p * v1.x;  o[u][5]  += p * v1.y;
                o[u][6]  += p * v1.z;  o[u][7]  += p * v1.w;
                o[u][8]  += p * v2.x;  o[u][9]  += p * v2.y;
                o[u][10] += p * v2.z;  o[u][11] += p * v2.w;
                o[u][12] += p * v3.x;  o[u][13] += p * v3.y;
                o[u][14] += p * v3.z;  o[u][15] += p * v3.w;
            }
        }
    }

    // Final normalization
    if (t == 0) {
        lrow[warp * 16 + g]     = l0;
        lrow[warp * 16 + g + 8] = l1;
    }
    __syncthreads();

#pragma unroll
    for (int u = 0; u < 4; u++) {
        const int row = rr + 16 * u;
        const float inv = 1.f / lrow[row];
        float* outp = &g_attn[(size_t)(qb + row) * (N_HEADS * HEAD_DIM) + h * HEAD_DIM + cx * 16];
#pragma unroll
        for (int q4 = 0; q4 < 4; q4++) {
            ((float4*)outp)[q4] = make_float4(o[u][q4 * 4 + 0] * inv, o[u][q4 * 4 + 1] * inv,
                                              o[u][q4 * 4 + 2] * inv, o[u][q4 * 4 + 3] * inv);
        }
    }
}

// ---------------------------------------------------------------------------
// Launch
// ---------------------------------------------------------------------------
extern "C" void kernel_launch(void* const* d_in, const int* in_sizes, int n_in,
                              void* d_out, int out_size)
{
    const float* hidden    = (const float*)d_in[0];
    const int*   positions = (const int*)  d_in[1];
    const float* w_qkv     = (const float*)d_in[2];
    const float* b_qkv     = (const float*)d_in[3];
    const float* w_o       = (const float*)d_in[4];
    float*       out       = (float*)d_out;

    float* qkv_ptr  = nullptr;
    float* attn_ptr = nullptr;
    cudaGetSymbolAddress((void**)&qkv_ptr,  g_qkv);
    cudaGetSymbolAddress((void**)&attn_ptr, g_attn);

    cudaFuncSetAttribute(attn_kernel,
                         cudaFuncAttributeMaxDynamicSharedMemorySize,
                         ATTN_SMEM_BYTES);

    // 1) QKV projection + bias (TF32 tensor cores)
    gemm_tf32_kernel<<<dim3(QKV_OUT / BN, T_DIM / BM), 256>>>(
        hidden, w_qkv, b_qkv, qkv_ptr, T_DIM, QKV_OUT, HIDDEN);

    // 2) RoPE on q + k heads
    rope_kernel<<<dim3(T_DIM, N_HEADS + N_KV), 64>>>(positions);

    // 3) Sliding-window GQA flash attention (QK on tensor cores)
    attn_kernel<<<dim3(T_DIM / AQ, N_HEADS), 128, ATTN_SMEM_BYTES>>>();

    // 4) Output projection (TF32 tensor cores)
    gemm_tf32_kernel<<<dim3(HIDDEN / BN, T_DIM / BM), 256>>>(
        attn_ptr, w_o, nullptr, out, T_DIM, HIDDEN, N_HEADS * HEAD_DIM);
}

// round 8
// speedup vs baseline: 3.3813x; 1.6597x over previous
#include <cuda_runtime.h>
#include <math.h>
#include <stdint.h>

// Problem constants
#define T_DIM    4096
#define HIDDEN   2048
#define N_HEADS  16
#define N_KV     4
#define HEAD_DIM 128
#define WINDOW   1024
#define QKV_OUT  3072           // (16 + 2*4) * 128
#define Q_SIZE   2048           // 16*128
#define KV_SIZE  512            // 4*128

// Scratch (no cudaMalloc allowed)
__device__ float g_qkv [(size_t)T_DIM * QKV_OUT];            // 50.3 MB
__device__ float g_attn[(size_t)T_DIM * N_HEADS * HEAD_DIM]; // 33.5 MB

__device__ __forceinline__ uint32_t f2tf32(float x) {
    uint32_t u;
    asm("cvt.rna.tf32.f32 %0, %1;" : "=r"(u) : "f"(x));
    return u;
}

__device__ __forceinline__ void mma_tf32(
    float& c0, float& c1, float& c2, float& c3,
    uint32_t a0, uint32_t a1, uint32_t a2, uint32_t a3,
    uint32_t b0, uint32_t b1)
{
    asm("mma.sync.aligned.m16n8k8.row.col.f32.tf32.tf32.f32 "
        "{%0,%1,%2,%3}, {%4,%5,%6,%7}, {%8,%9}, {%0,%1,%2,%3};"
        : "+f"(c0), "+f"(c1), "+f"(c2), "+f"(c3)
        : "r"(a0), "r"(a1), "r"(a2), "r"(a3), "r"(b0), "r"(b1));
}

// ---------------------------------------------------------------------------
// TF32 tensor-core GEMM: C[M,N] = A[M,K] @ B[K,N] (+ bias[N])  (unchanged)
// ---------------------------------------------------------------------------
#define BM 128
#define BN 128
#define BK 16
#define AS_STRIDE 20
#define BS_STRIDE 129

__global__ __launch_bounds__(256) void gemm_tf32_kernel(
    const float* __restrict__ A, const float* __restrict__ B,
    const float* __restrict__ bias, float* __restrict__ C,
    int M, int N, int K)
{
    __shared__ uint32_t As[2][BM][AS_STRIDE];
    __shared__ uint32_t Bs[2][BK][BS_STRIDE];

    const int tid = threadIdx.x;
    const int m0  = blockIdx.y * BM;
    const int n0  = blockIdx.x * BN;

    const int wid  = tid >> 5;
    const int lane = tid & 31;
    const int wm   = wid >> 2;
    const int wn   = wid & 3;
    const int g    = lane >> 2;
    const int t    = lane & 3;

    float c[4][4][4];
#pragma unroll
    for (int i = 0; i < 4; i++)
#pragma unroll
        for (int j = 0; j < 4; j++)
#pragma unroll
            for (int u = 0; u < 4; u++) c[i][j][u] = 0.f;

    const int arow = tid >> 1;
    const int acol = (tid & 1) * 8;
    const int brow = tid >> 4;
    const int bcol = (tid & 15) * 8;

    const float* Ap = A + (size_t)(m0 + arow) * K + acol;
    const float* Bp = B + (size_t)brow * N + n0 + bcol;

    {
        float4 av0 = *(const float4*)(Ap + 0);
        float4 av1 = *(const float4*)(Ap + 4);
        float4 bv0 = *(const float4*)(Bp + 0);
        float4 bv1 = *(const float4*)(Bp + 4);
        uint4 ua0 = make_uint4(f2tf32(av0.x), f2tf32(av0.y), f2tf32(av0.z), f2tf32(av0.w));
        uint4 ua1 = make_uint4(f2tf32(av1.x), f2tf32(av1.y), f2tf32(av1.z), f2tf32(av1.w));
        *(uint4*)&As[0][arow][acol + 0] = ua0;
        *(uint4*)&As[0][arow][acol + 4] = ua1;
        Bs[0][brow][bcol + 0] = f2tf32(bv0.x);
        Bs[0][brow][bcol + 1] = f2tf32(bv0.y);
        Bs[0][brow][bcol + 2] = f2tf32(bv0.z);
        Bs[0][brow][bcol + 3] = f2tf32(bv0.w);
        Bs[0][brow][bcol + 4] = f2tf32(bv1.x);
        Bs[0][brow][bcol + 5] = f2tf32(bv1.y);
        Bs[0][brow][bcol + 6] = f2tf32(bv1.z);
        Bs[0][brow][bcol + 7] = f2tf32(bv1.w);
    }
    __syncthreads();

    int cur = 0;
    for (int k0 = 0; k0 < K; k0 += BK) {
        const bool has_next = (k0 + BK) < K;
        float4 av0, av1, bv0, bv1;
        if (has_next) {
            av0 = *(const float4*)(Ap + BK + 0);
            av1 = *(const float4*)(Ap + BK + 4);
            bv0 = *(const float4*)(Bp + (size_t)BK * N + 0);
            bv1 = *(const float4*)(Bp + (size_t)BK * N + 4);
        }

#pragma unroll
        for (int ks = 0; ks < 2; ks++) {
            const int kk = ks * 8;
            uint32_t bf0[4], bf1[4];
#pragma unroll
            for (int nt = 0; nt < 4; nt++) {
                const int col = wn * 32 + nt * 8 + g;
                bf0[nt] = Bs[cur][kk + t][col];
                bf1[nt] = Bs[cur][kk + 4 + t][col];
            }
#pragma unroll
            for (int mt = 0; mt < 4; mt++) {
                const int r = wm * 64 + mt * 16 + g;
                uint32_t a0 = As[cur][r][kk + t];
                uint32_t a1 = As[cur][r + 8][kk + t];
                uint32_t a2 = As[cur][r][kk + t + 4];
                uint32_t a3 = As[cur][r + 8][kk + t + 4];
#pragma unroll
                for (int nt = 0; nt < 4; nt++)
                    mma_tf32(c[mt][nt][0], c[mt][nt][1], c[mt][nt][2], c[mt][nt][3],
                             a0, a1, a2, a3, bf0[nt], bf1[nt]);
            }
        }

        if (has_next) {
            const int nxt = cur ^ 1;
            uint4 ua0 = make_uint4(f2tf32(av0.x), f2tf32(av0.y), f2tf32(av0.z), f2tf32(av0.w));
            uint4 ua1 = make_uint4(f2tf32(av1.x), f2tf32(av1.y), f2tf32(av1.z), f2tf32(av1.w));
            *(uint4*)&As[nxt][arow][acol + 0] = ua0;
            *(uint4*)&As[nxt][arow][acol + 4] = ua1;
            Bs[nxt][brow][bcol + 0] = f2tf32(bv0.x);
            Bs[nxt][brow][bcol + 1] = f2tf32(bv0.y);
            Bs[nxt][brow][bcol + 2] = f2tf32(bv0.z);
            Bs[nxt][brow][bcol + 3] = f2tf32(bv0.w);
            Bs[nxt][brow][bcol + 4] = f2tf32(bv1.x);
            Bs[nxt][brow][bcol + 5] = f2tf32(bv1.y);
            Bs[nxt][brow][bcol + 6] = f2tf32(bv1.z);
            Bs[nxt][brow][bcol + 7] = f2tf32(bv1.w);
            __syncthreads();
            cur = nxt;
        }
        Ap += BK;
        Bp += (size_t)BK * N;
    }

#pragma unroll
    for (int mt = 0; mt < 4; mt++) {
#pragma unroll
        for (int nt = 0; nt < 4; nt++) {
            const int row0 = m0 + wm * 64 + mt * 16 + g;
            const int row1 = row0 + 8;
            const int col  = n0 + wn * 32 + nt * 8 + 2 * t;
            float bb0 = bias ? bias[col]     : 0.f;
            float bb1 = bias ? bias[col + 1] : 0.f;
            float2 v0 = make_float2(c[mt][nt][0] + bb0, c[mt][nt][1] + bb1);
            float2 v1 = make_float2(c[mt][nt][2] + bb0, c[mt][nt][3] + bb1);
            *(float2*)&C[(size_t)row0 * N + col] = v0;
            *(float2*)&C[(size_t)row1 * N + col] = v1;
        }
    }
}

// ---------------------------------------------------------------------------
// RoPE (unchanged)
// ---------------------------------------------------------------------------
__global__ void rope_kernel(const int* __restrict__ positions)
{
    const int t  = blockIdx.x;
    const int hh = blockIdx.y;
    const int d  = threadIdx.x;

    const size_t base = (size_t)t * QKV_OUT +
        ((hh < N_HEADS) ? hh * HEAD_DIM : Q_SIZE + (hh - N_HEADS) * HEAD_DIM);

    const float pos = (float)positions[t];
    const float inv_freq = powf(100000.0f, -((float)d) * (1.0f / 64.0f));
    float sn, cs;
    sincosf(pos * inv_freq, &sn, &cs);

    const float x1 = g_qkv[base + d];
    const float x2 = g_qkv[base + d + 64];
    g_qkv[base + d]      = x1 * cs - x2 * sn;
    g_qkv[base + d + 64] = x2 * cs + x1 * sn;
}

// ---------------------------------------------------------------------------
// Flash attention: QK^T AND PV on tf32 tensor cores.
// Block: 64 queries x 1 head, 128 threads (4 warps). Warp w owns rows
// [16w,16w+16). O lives in mma fragments; rescale factors apply in-register.
// ---------------------------------------------------------------------------
#define AQ 64
#define AK 64
#define KS_STRIDE 132   // bank 4g+t for QK B-frags: conflict-free
#define VS_STRIDE 136   // bank 8(t+nt)+g for PV B-frags: conflict-free
#define PS_STRIDE 68    // bank 4g+t for PV A-frags: conflict-free

#define ATTN_SMEM_BYTES ((AK * KS_STRIDE + AK * VS_STRIDE + AQ * PS_STRIDE) * 4)

__global__ __launch_bounds__(128, 2) void attn_kernel()
{
    extern __shared__ uint32_t smraw[];
    uint32_t* Ks = smraw;                       // 64 x 132 tf32 bits
    uint32_t* Vs = Ks + AK * KS_STRIDE;         // 64 x 136 tf32 bits
    uint32_t* Ps = Vs + AK * VS_STRIDE;         // 64 x 68  tf32 bits

    const int tid  = threadIdx.x;
    const int h    = blockIdx.y;
    const int qb   = blockIdx.x * AQ;
    const int kvh  = h >> 2;

    const int warp = tid >> 5;
    const int lane = tid & 31;
    const int g    = lane >> 2;        // 0..7
    const int t    = lane & 3;         // 0..3

    const int i0 = qb + warp * 16 + g;
    const int i1 = i0 + 8;

    // Q fragments in registers: 16 k-steps x 4 regs (tf32)
    uint32_t qa[16][4];
    {
        const float* q0p = &g_qkv[(size_t)i0 * QKV_OUT + h * HEAD_DIM];
        const float* q1p = q0p + (size_t)8 * QKV_OUT;
#pragma unroll
        for (int ks = 0; ks < 16; ks++) {
            qa[ks][0] = f2tf32(q0p[8 * ks + t]);
            qa[ks][1] = f2tf32(q1p[8 * ks + t]);
            qa[ks][2] = f2tf32(q0p[8 * ks + t + 4]);
            qa[ks][3] = f2tf32(q1p[8 * ks + t + 4]);
        }
    }

    // O fragments: 16 n8-tiles over HEAD_DIM, 4 regs each
    float o[16][4];
#pragma unroll
    for (int nt = 0; nt < 16; nt++)
#pragma unroll
        for (int u = 0; u < 4; u++) o[nt][u] = 0.f;

    float m0 = -1e30f, m1 = -1e30f, l0 = 0.f, l1 = 0.f;

    int lo = qb - WINDOW;
    if (lo < 0) lo = 0;
    const float scale = 0.08838834764831845f;

    for (int kt = lo; kt <= qb; kt += AK) {
        __syncthreads();   // previous iteration's Ks/Vs reads complete
        // Load K and V tiles (both tf32-converted)
#pragma unroll
        for (int it = 0; it < 16; it++) {
            int idx = it * 128 + tid;       // 0..2047
            int r   = idx >> 5;
            int c4  = idx & 31;
            size_t base = (size_t)(kt + r) * QKV_OUT + Q_SIZE + kvh * HEAD_DIM + c4 * 4;
            float4 kv = *(const float4*)&g_qkv[base];
            float4 vv = *(const float4*)&g_qkv[base + KV_SIZE];
            uint4 uk = make_uint4(f2tf32(kv.x), f2tf32(kv.y), f2tf32(kv.z), f2tf32(kv.w));
            uint4 uv = make_uint4(f2tf32(vv.x), f2tf32(vv.y), f2tf32(vv.z), f2tf32(vv.w));
            *(uint4*)&Ks[r * KS_STRIDE + c4 * 4] = uk;
            *(uint4*)&Vs[r * VS_STRIDE + c4 * 4] = uv;
        }
        __syncthreads();

        // ---- S = Q @ K^T : 8 n-tiles (over AK) x 16 k-steps ----
        float s[8][4];
#pragma unroll
        for (int nt = 0; nt < 8; nt++)
#pragma unroll
            for (int u = 0; u < 4; u++) s[nt][u] = 0.f;

#pragma unroll
        for (int ks = 0; ks < 16; ks++) {
#pragma unroll
            for (int nt = 0; nt < 8; nt++) {
                uint32_t b0 = Ks[(8 * nt + g) * KS_STRIDE + 8 * ks + t];
                uint32_t b1 = Ks[(8 * nt + g) * KS_STRIDE + 8 * ks + t + 4];
                mma_tf32(s[nt][0], s[nt][1], s[nt][2], s[nt][3],
                         qa[ks][0], qa[ks][1], qa[ks][2], qa[ks][3], b0, b1);
            }
        }

        // ---- mask + scale + fragment softmax ----
        float rm0 = -INFINITY, rm1 = -INFINITY;
#pragma unroll
        for (int nt = 0; nt < 8; nt++) {
#pragma unroll
            for (int e = 0; e < 2; e++) {
                int j = kt + nt * 8 + 2 * t + e;
                bool v0 = (j <= i0) && (j + WINDOW >= i0);
                bool v1 = (j <= i1) && (j + WINDOW >= i1);
                s[nt][e]     = v0 ? s[nt][e]     * scale : -INFINITY;
                s[nt][2 + e] = v1 ? s[nt][2 + e] * scale : -INFINITY;
                rm0 = fmaxf(rm0, s[nt][e]);
                rm1 = fmaxf(rm1, s[nt][2 + e]);
            }
        }
        rm0 = fmaxf(rm0, __shfl_xor_sync(0xffffffffu, rm0, 1));
        rm0 = fmaxf(rm0, __shfl_xor_sync(0xffffffffu, rm0, 2));
        rm1 = fmaxf(rm1, __shfl_xor_sync(0xffffffffu, rm1, 1));
        rm1 = fmaxf(rm1, __shfl_xor_sync(0xffffffffu, rm1, 2));

        float mn0 = fmaxf(m0, rm0), mn1 = fmaxf(m1, rm1);
        float c0 = __expf(m0 - mn0), c1 = __expf(m1 - mn1);
        float rs0 = 0.f, rs1 = 0.f;
#pragma unroll
        for (int nt = 0; nt < 8; nt++) {
            float p00 = __expf(s[nt][0] - mn0);
            float p01 = __expf(s[nt][1] - mn0);
            float p10 = __expf(s[nt][2] - mn1);
            float p11 = __expf(s[nt][3] - mn1);
            // store P as tf32 bits (warp-local rows)
            uint32_t* p0 = &Ps[(warp * 16 + g) * PS_STRIDE + nt * 8 + 2 * t];
            uint32_t* p1 = &Ps[(warp * 16 + g + 8) * PS_STRIDE + nt * 8 + 2 * t];
            p0[0] = f2tf32(p00);
            p0[1] = f2tf32(p01);
            p1[0] = f2tf32(p10);
            p1[1] = f2tf32(p11);
            rs0 += p00 + p01;
            rs1 += p10 + p11;
        }
        rs0 += __shfl_xor_sync(0xffffffffu, rs0, 1);
        rs0 += __shfl_xor_sync(0xffffffffu, rs0, 2);
        rs1 += __shfl_xor_sync(0xffffffffu, rs1, 1);
        rs1 += __shfl_xor_sync(0xffffffffu, rs1, 2);

        l0 = l0 * c0 + rs0;
        l1 = l1 * c1 + rs1;
        m0 = mn0;
        m1 = mn1;

        // rescale O fragments in-register (rows g -> c0, rows g+8 -> c1)
#pragma unroll
        for (int nt = 0; nt < 16; nt++) {
            o[nt][0] *= c0;
            o[nt][1] *= c0;
            o[nt][2] *= c1;
            o[nt][3] *= c1;
        }

        __syncwarp();      // P smem writes -> reads (warp-local)

        // ---- O += P @ V : 8 k-steps x 16 n-tiles (over HEAD_DIM) ----
#pragma unroll
        for (int ks = 0; ks < 8; ks++) {
            const int rbase = (warp * 16 + g) * PS_STRIDE + 8 * ks;
            uint32_t a0 = Ps[rbase + t];
            uint32_t a1 = Ps[rbase + 8 * PS_STRIDE + t];
            uint32_t a2 = Ps[rbase + t + 4];
            uint32_t a3 = Ps[rbase + 8 * PS_STRIDE + t + 4];
#pragma unroll
            for (int nt = 0; nt < 16; nt++) {
                uint32_t b0 = Vs[(8 * ks + t) * VS_STRIDE + 8 * nt + g];
                uint32_t b1 = Vs[(8 * ks + t + 4) * VS_STRIDE + 8 * nt + g];
                mma_tf32(o[nt][0], o[nt][1], o[nt][2], o[nt][3],
                         a0, a1, a2, a3, b0, b1);
            }
        }
        __syncwarp();      // Ps reads complete before next iteration overwrites
    }

    // Final normalization + store (fragment layout: rows i0/i1, cols 8nt+2t)
    const float inv0 = 1.f / l0;
    const float inv1 = 1.f / l1;
    float* out0 = &g_attn[(size_t)i0 * (N_HEADS * HEAD_DIM) + h * HEAD_DIM];
    float* out1 = &g_attn[(size_t)i1 * (N_HEADS * HEAD_DIM) + h * HEAD_DIM];
#pragma unroll
    for (int nt = 0; nt < 16; nt++) {
        const int col = nt * 8 + 2 * t;
        *(float2*)&out0[col] = make_float2(o[nt][0] * inv0, o[nt][1] * inv0);
        *(float2*)&out1[col] = make_float2(o[nt][2] * inv1, o[nt][3] * inv1);
    }
}

// ---------------------------------------------------------------------------
// Launch
// ---------------------------------------------------------------------------
extern "C" void kernel_launch(void* const* d_in, const int* in_sizes, int n_in,
                              void* d_out, int out_size)
{
    const float* hidden    = (const float*)d_in[0];
    const int*   positions = (const int*)  d_in[1];
    const float* w_qkv     = (const float*)d_in[2];
    const float* b_qkv     = (const float*)d_in[3];
    const float* w_o       = (const float*)d_in[4];
    float*       out       = (float*)d_out;

    float* qkv_ptr  = nullptr;
    float* attn_ptr = nullptr;
    cudaGetSymbolAddress((void**)&qkv_ptr,  g_qkv);
    cudaGetSymbolAddress((void**)&attn_ptr, g_attn);

    cudaFuncSetAttribute(attn_kernel,
                         cudaFuncAttributeMaxDynamicSharedMemorySize,
                         ATTN_SMEM_BYTES);

    // 1) QKV projection + bias (TF32 tensor cores)
    gemm_tf32_kernel<<<dim3(QKV_OUT / BN, T_DIM / BM), 256>>>(
        hidden, w_qkv, b_qkv, qkv_ptr, T_DIM, QKV_OUT, HIDDEN);

    // 2) RoPE on q + k heads
    rope_kernel<<<dim3(T_DIM, N_HEADS + N_KV), 64>>>(positions);

    // 3) Sliding-window GQA flash attention (QK + PV on tensor cores)
    attn_kernel<<<dim3(T_DIM / AQ, N_HEADS), 128, ATTN_SMEM_BYTES>>>();

    // 4) Output projection (TF32 tensor cores)
    gemm_tf32_kernel<<<dim3(HIDDEN / BN, T_DIM / BM), 256>>>(
        attn_ptr, w_o, nullptr, out, T_DIM, HIDDEN, N_HEADS * HEAD_DIM);
}

// round 14
// speedup vs baseline: 3.8276x; 1.1320x over previous
#include <cuda_runtime.h>
#include <math.h>
#include <stdint.h>

// Problem constants
#define T_DIM    4096
#define HIDDEN   2048
#define N_HEADS  16
#define N_KV     4
#define HEAD_DIM 128
#define WINDOW   1024
#define QKV_OUT  3072           // (16 + 2*4) * 128
#define Q_SIZE   2048           // 16*128
#define KV_SIZE  512            // 4*128

// Scratch (no cudaMalloc allowed)
__device__ float g_qkv [(size_t)T_DIM * QKV_OUT];            // 50.3 MB
__device__ float g_attn[(size_t)T_DIM * N_HEADS * HEAD_DIM]; // 33.5 MB

__device__ __forceinline__ uint32_t f2tf32(float x) {
    uint32_t u;
    asm("cvt.rna.tf32.f32 %0, %1;" : "=r"(u) : "f"(x));
    return u;
}

__device__ __forceinline__ void mma_tf32(
    float& c0, float& c1, float& c2, float& c3,
    uint32_t a0, uint32_t a1, uint32_t a2, uint32_t a3,
    uint32_t b0, uint32_t b1)
{
    asm("mma.sync.aligned.m16n8k8.row.col.f32.tf32.tf32.f32 "
        "{%0,%1,%2,%3}, {%4,%5,%6,%7}, {%8,%9}, {%0,%1,%2,%3};"
        : "+f"(c0), "+f"(c1), "+f"(c2), "+f"(c3)
        : "r"(a0), "r"(a1), "r"(a2), "r"(a3), "r"(b0), "r"(b1));
}

__device__ __forceinline__ uint4 cvt4(float4 v) {
    return make_uint4(f2tf32(v.x), f2tf32(v.y), f2tf32(v.z), f2tf32(v.w));
}

// ---------------------------------------------------------------------------
// TF32 tensor-core GEMM: C[M,N] = A[M,K] @ B[K,N] (+ bias[N])
// 128x128 block, BK=32, 256 threads (8 warps in 2x4), warp tile 64x32.
// Conflict-free fragment strides: A stride 36 (bank 4g+t), B stride 136
// (bank 8t+g). Double-buffered smem (dynamic, 70 KB), register-staged loads.
// ---------------------------------------------------------------------------
#define BM 128
#define BN 128
#define BK 32
#define AS_STRIDE 36
#define BS_STRIDE 136
#define GEMM_SMEM_BYTES ((2 * BM * AS_STRIDE + 2 * BK * BS_STRIDE) * 4)

__global__ __launch_bounds__(256, 2) void gemm_tf32_kernel(
    const float* __restrict__ A, const float* __restrict__ B,
    const float* __restrict__ bias, float* __restrict__ C,
    int M, int N, int K)
{
    extern __shared__ uint32_t gsm[];
    uint32_t* Asm = gsm;                          // [2][BM][AS_STRIDE]
    uint32_t* Bsm = gsm + 2 * BM * AS_STRIDE;     // [2][BK][BS_STRIDE]

    const int tid = threadIdx.x;
    const int m0  = blockIdx.y * BM;
    const int n0  = blockIdx.x * BN;

    const int wid  = tid >> 5;
    const int lane = tid & 31;
    const int wm   = wid >> 2;        // 0..1
    const int wn   = wid & 3;         // 0..3
    const int g    = lane >> 2;       // 0..7
    const int t    = lane & 3;        // 0..3

    float c[4][4][4];
#pragma unroll
    for (int i = 0; i < 4; i++)
#pragma unroll
        for (int j = 0; j < 4; j++)
#pragma unroll
            for (int u = 0; u < 4; u++) c[i][j][u] = 0.f;

    // Loaders: A tile 128x32 (row tid>>1, cols (tid&1)*16 + 0..15)
    //          B tile 32x128 (row tid>>3, cols (tid&7)*16 + 0..15)
    const int arow = tid >> 1;
    const int acol = (tid & 1) * 16;
    const int brow = tid >> 3;
    const int bcol = (tid & 7) * 16;

    const float* Ap = A + (size_t)(m0 + arow) * K + acol;
    const float* Bp = B + (size_t)brow * N + n0 + bcol;

    uint32_t* Arow0 = &Asm[arow * AS_STRIDE + acol];
    uint32_t* Brow0 = &Bsm[brow * BS_STRIDE + bcol];

    // Preload tile 0 into buffer 0
    {
        float4 a0 = *(const float4*)(Ap + 0);
        float4 a1 = *(const float4*)(Ap + 4);
        float4 a2 = *(const float4*)(Ap + 8);
        float4 a3 = *(const float4*)(Ap + 12);
        float4 b0 = *(const float4*)(Bp + 0);
        float4 b1 = *(const float4*)(Bp + 4);
        float4 b2 = *(const float4*)(Bp + 8);
        float4 b3 = *(const float4*)(Bp + 12);
        *(uint4*)(Arow0 + 0)  = cvt4(a0);
        *(uint4*)(Arow0 + 4)  = cvt4(a1);
        *(uint4*)(Arow0 + 8)  = cvt4(a2);
        *(uint4*)(Arow0 + 12) = cvt4(a3);
        *(uint4*)(Brow0 + 0)  = cvt4(b0);
        *(uint4*)(Brow0 + 4)  = cvt4(b1);
        *(uint4*)(Brow0 + 8)  = cvt4(b2);
        *(uint4*)(Brow0 + 12) = cvt4(b3);
    }
    __syncthreads();

    int cur = 0;
    for (int k0 = 0; k0 < K; k0 += BK) {
        const bool has_next = (k0 + BK) < K;
        float4 a0, a1, a2, a3, b0, b1, b2, b3;
        if (has_next) {
            a0 = *(const float4*)(Ap + BK + 0);
            a1 = *(const float4*)(Ap + BK + 4);
            a2 = *(const float4*)(Ap + BK + 8);
            a3 = *(const float4*)(Ap + BK + 12);
            const float* Bn = Bp + (size_t)BK * N;
            b0 = *(const float4*)(Bn + 0);
            b1 = *(const float4*)(Bn + 4);
            b2 = *(const float4*)(Bn + 8);
            b3 = *(const float4*)(Bn + 12);
        }

        const uint32_t* Ab = Asm + cur * (BM * AS_STRIDE);
        const uint32_t* Bb = Bsm + cur * (BK * BS_STRIDE);
#pragma unroll
        for (int ks = 0; ks < 4; ks++) {
            const int kk = ks * 8;
            uint32_t bf0[4], bf1[4];
#pragma unroll
            for (int nt = 0; nt < 4; nt++) {
                const int col = wn * 32 + nt * 8 + g;
                bf0[nt] = Bb[(kk + t) * BS_STRIDE + col];
                bf1[nt] = Bb[(kk + 4 + t) * BS_STRIDE + col];
            }
#pragma unroll
            for (int mt = 0; mt < 4; mt++) {
                const int r = wm * 64 + mt * 16 + g;
                uint32_t fa0 = Ab[r * AS_STRIDE + kk + t];
                uint32_t fa1 = Ab[(r + 8) * AS_STRIDE + kk + t];
                uint32_t fa2 = Ab[r * AS_STRIDE + kk + t + 4];
                uint32_t fa3 = Ab[(r + 8) * AS_STRIDE + kk + t + 4];
#pragma unroll
                for (int nt = 0; nt < 4; nt++)
                    mma_tf32(c[mt][nt][0], c[mt][nt][1], c[mt][nt][2], c[mt][nt][3],
                             fa0, fa1, fa2, fa3, bf0[nt], bf1[nt]);
            }
        }

        if (has_next) {
            const int nxt = cur ^ 1;
            uint32_t* Ad = Arow0 + nxt * (BM * AS_STRIDE);
            uint32_t* Bd = Brow0 + nxt * (BK * BS_STRIDE);
            *(uint4*)(Ad + 0)  = cvt4(a0);
            *(uint4*)(Ad + 4)  = cvt4(a1);
            *(uint4*)(Ad + 8)  = cvt4(a2);
            *(uint4*)(Ad + 12) = cvt4(a3);
            *(uint4*)(Bd + 0)  = cvt4(b0);
            *(uint4*)(Bd + 4)  = cvt4(b1);
            *(uint4*)(Bd + 8)  = cvt4(b2);
            *(uint4*)(Bd + 12) = cvt4(b3);
            __syncthreads();
            cur = nxt;
        }
        Ap += BK;
        Bp += (size_t)BK * N;
    }

    // Epilogue
#pragma unroll
    for (int mt = 0; mt < 4; mt++) {
#pragma unroll
        for (int nt = 0; nt < 4; nt++) {
            const int row0 = m0 + wm * 64 + mt * 16 + g;
            const int row1 = row0 + 8;
            const int col  = n0 + wn * 32 + nt * 8 + 2 * t;
            float bb0 = bias ? bias[col]     : 0.f;
            float bb1 = bias ? bias[col + 1] : 0.f;
            float2 v0 = make_float2(c[mt][nt][0] + bb0, c[mt][nt][1] + bb1);
            float2 v1 = make_float2(c[mt][nt][2] + bb0, c[mt][nt][3] + bb1);
            *(float2*)&C[(size_t)row0 * N + col] = v0;
            *(float2*)&C[(size_t)row1 * N + col] = v1;
        }
    }
}

// ---------------------------------------------------------------------------
// RoPE (unchanged)
// ---------------------------------------------------------------------------
__global__ void rope_kernel(const int* __restrict__ positions)
{
    const int t  = blockIdx.x;
    const int hh = blockIdx.y;
    const int d  = threadIdx.x;

    const size_t base = (size_t)t * QKV_OUT +
        ((hh < N_HEADS) ? hh * HEAD_DIM : Q_SIZE + (hh - N_HEADS) * HEAD_DIM);

    const float pos = (float)positions[t];
    const float inv_freq = powf(100000.0f, -((float)d) * (1.0f / 64.0f));
    float sn, cs;
    sincosf(pos * inv_freq, &sn, &cs);

    const float x1 = g_qkv[base + d];
    const float x2 = g_qkv[base + d + 64];
    g_qkv[base + d]      = x1 * cs - x2 * sn;
    g_qkv[base + d + 64] = x2 * cs + x1 * sn;
}

// ---------------------------------------------------------------------------
// Flash attention: QK^T AND PV on tf32 tensor cores (unchanged from R8 winner)
// ---------------------------------------------------------------------------
#define AQ 64
#define AK 64
#define KS_STRIDE 132   // bank 4g+t for QK B-frags: conflict-free
#define VS_STRIDE 136   // bank 8t+g for PV B-frags: conflict-free
#define PS_STRIDE 68    // bank 4g+t for PV A-frags: conflict-free

#define ATTN_SMEM_BYTES ((AK * KS_STRIDE + AK * VS_STRIDE + AQ * PS_STRIDE) * 4)

__global__ __launch_bounds__(128, 2) void attn_kernel()
{
    extern __shared__ uint32_t smraw[];
    uint32_t* Ks = smraw;                       // 64 x 132 tf32 bits
    uint32_t* Vs = Ks + AK * KS_STRIDE;         // 64 x 136 tf32 bits
    uint32_t* Ps = Vs + AK * VS_STRIDE;         // 64 x 68  tf32 bits

    const int tid  = threadIdx.x;
    const int h    = blockIdx.y;
    const int qb   = blockIdx.x * AQ;
    const int kvh  = h >> 2;

    const int warp = tid >> 5;
    const int lane = tid & 31;
    const int g    = lane >> 2;        // 0..7
    const int t    = lane & 3;         // 0..3

    const int i0 = qb + warp * 16 + g;
    const int i1 = i0 + 8;

    // Q fragments in registers: 16 k-steps x 4 regs (tf32)
    uint32_t qa[16][4];
    {
        const float* q0p = &g_qkv[(size_t)i0 * QKV_OUT + h * HEAD_DIM];
        const float* q1p = q0p + (size_t)8 * QKV_OUT;
#pragma unroll
        for (int ks = 0; ks < 16; ks++) {
            qa[ks][0] = f2tf32(q0p[8 * ks + t]);
            qa[ks][1] = f2tf32(q1p[8 * ks + t]);
            qa[ks][2] = f2tf32(q0p[8 * ks + t + 4]);
            qa[ks][3] = f2tf32(q1p[8 * ks + t + 4]);
        }
    }

    // O fragments: 16 n8-tiles over HEAD_DIM, 4 regs each
    float o[16][4];
#pragma unroll
    for (int nt = 0; nt < 16; nt++)
#pragma unroll
        for (int u = 0; u < 4; u++) o[nt][u] = 0.f;

    float m0 = -1e30f, m1 = -1e30f, l0 = 0.f, l1 = 0.f;

    int lo = qb - WINDOW;
    if (lo < 0) lo = 0;
    const float scale = 0.08838834764831845f;

    for (int kt = lo; kt <= qb; kt += AK) {
        __syncthreads();
#pragma unroll
        for (int it = 0; it < 16; it++) {
            int idx = it * 128 + tid;
            int r   = idx >> 5;
            int c4  = idx & 31;
            size_t base = (size_t)(kt + r) * QKV_OUT + Q_SIZE + kvh * HEAD_DIM + c4 * 4;
            float4 kv = *(const float4*)&g_qkv[base];
            float4 vv = *(const float4*)&g_qkv[base + KV_SIZE];
            *(uint4*)&Ks[r * KS_STRIDE + c4 * 4] = cvt4(kv);
            *(uint4*)&Vs[r * VS_STRIDE + c4 * 4] = cvt4(vv);
        }
        __syncthreads();

        // ---- S = Q @ K^T ----
        float s[8][4];
#pragma unroll
        for (int nt = 0; nt < 8; nt++)
#pragma unroll
            for (int u = 0; u < 4; u++) s[nt][u] = 0.f;

#pragma unroll
        for (int ks = 0; ks < 16; ks++) {
#pragma unroll
            for (int nt = 0; nt < 8; nt++) {
                uint32_t b0 = Ks[(8 * nt + g) * KS_STRIDE + 8 * ks + t];
                uint32_t b1 = Ks[(8 * nt + g) * KS_STRIDE + 8 * ks + t + 4];
                mma_tf32(s[nt][0], s[nt][1], s[nt][2], s[nt][3],
                         qa[ks][0], qa[ks][1], qa[ks][2], qa[ks][3], b0, b1);
            }
        }

        // ---- mask + scale + fragment softmax ----
        float rm0 = -INFINITY, rm1 = -INFINITY;
#pragma unroll
        for (int nt = 0; nt < 8; nt++) {
#pragma unroll
            for (int e = 0; e < 2; e++) {
                int j = kt + nt * 8 + 2 * t + e;
                bool v0 = (j <= i0) && (j + WINDOW >= i0);
                bool v1 = (j <= i1) && (j + WINDOW >= i1);
                s[nt][e]     = v0 ? s[nt][e]     * scale : -INFINITY;
                s[nt][2 + e] = v1 ? s[nt][2 + e] * scale : -INFINITY;
                rm0 = fmaxf(rm0, s[nt][e]);
                rm1 = fmaxf(rm1, s[nt][2 + e]);
            }
        }
        rm0 = fmaxf(rm0, __shfl_xor_sync(0xffffffffu, rm0, 1));
        rm0 = fmaxf(rm0, __shfl_xor_sync(0xffffffffu, rm0, 2));
        rm1 = fmaxf(rm1, __shfl_xor_sync(0xffffffffu, rm1, 1));
        rm1 = fmaxf(rm1, __shfl_xor_sync(0xffffffffu, rm1, 2));

        float mn0 = fmaxf(m0, rm0), mn1 = fmaxf(m1, rm1);
        float c0 = __expf(m0 - mn0), c1 = __expf(m1 - mn1);
        float rs0 = 0.f, rs1 = 0.f;
#pragma unroll
        for (int nt = 0; nt < 8; nt++) {
            float p00 = __expf(s[nt][0] - mn0);
            float p01 = __expf(s[nt][1] - mn0);
            float p10 = __expf(s[nt][2] - mn1);
            float p11 = __expf(s[nt][3] - mn1);
            uint32_t* p0 = &Ps[(warp * 16 + g) * PS_STRIDE + nt * 8 + 2 * t];
            uint32_t* p1 = &Ps[(warp * 16 + g + 8) * PS_STRIDE + nt * 8 + 2 * t];
            p0[0] = f2tf32(p00);
            p0[1] = f2tf32(p01);
            p1[0] = f2tf32(p10);
            p1[1] = f2tf32(p11);
            rs0 += p00 + p01;
            rs1 += p10 + p11;
        }
        rs0 += __shfl_xor_sync(0xffffffffu, rs0, 1);
        rs0 += __shfl_xor_sync(0xffffffffu, rs0, 2);
        rs1 += __shfl_xor_sync(0xffffffffu, rs1, 1);
        rs1 += __shfl_xor_sync(0xffffffffu, rs1, 2);

        l0 = l0 * c0 + rs0;
        l1 = l1 * c1 + rs1;
        m0 = mn0;
        m1 = mn1;

#pragma unroll
        for (int nt = 0; nt < 16; nt++) {
            o[nt][0] *= c0;
            o[nt][1] *= c0;
            o[nt][2] *= c1;
            o[nt][3] *= c1;
        }

        __syncwarp();

        // ---- O += P @ V ----
#pragma unroll
        for (int ks = 0; ks < 8; ks++) {
            const int rbase = (warp * 16 + g) * PS_STRIDE + 8 * ks;
            uint32_t a0 = Ps[rbase + t];
            uint32_t a1 = Ps[rbase + 8 * PS_STRIDE + t];
            uint32_t a2 = Ps[rbase + t + 4];
            uint32_t a3 = Ps[rbase + 8 * PS_STRIDE + t + 4];
#pragma unroll
            for (int nt = 0; nt < 16; nt++) {
                uint32_t b0 = Vs[(8 * ks + t) * VS_STRIDE + 8 * nt + g];
                uint32_t b1 = Vs[(8 * ks + t + 4) * VS_STRIDE + 8 * nt + g];
                mma_tf32(o[nt][0], o[nt][1], o[nt][2], o[nt][3],
                         a0, a1, a2, a3, b0, b1);
            }
        }
        __syncwarp();
    }

    const float inv0 = 1.f / l0;
    const float inv1 = 1.f / l1;
    float* out0 = &g_attn[(size_t)i0 * (N_HEADS * HEAD_DIM) + h * HEAD_DIM];
    float* out1 = &g_attn[(size_t)i1 * (N_HEADS * HEAD_DIM) + h * HEAD_DIM];
#pragma unroll
    for (int nt = 0; nt < 16; nt++) {
        const int col = nt * 8 + 2 * t;
        *(float2*)&out0[col] = make_float2(o[nt][0] * inv0, o[nt][1] * inv0);
        *(float2*)&out1[col] = make_float2(o[nt][2] * inv1, o[nt][3] * inv1);
    }
}

// ---------------------------------------------------------------------------
// Launch
// ---------------------------------------------------------------------------
extern "C" void kernel_launch(void* const* d_in, const int* in_sizes, int n_in,
                              void* d_out, int out_size)
{
    const float* hidden    = (const float*)d_in[0];
    const int*   positions = (const int*)  d_in[1];
    const float* w_qkv     = (const float*)d_in[2];
    const float* b_qkv     = (const float*)d_in[3];
    const float* w_o       = (const float*)d_in[4];
    float*       out       = (float*)d_out;

    float* qkv_ptr  = nullptr;
    float* attn_ptr = nullptr;
    cudaGetSymbolAddress((void**)&qkv_ptr,  g_qkv);
    cudaGetSymbolAddress((void**)&attn_ptr, g_attn);

    cudaFuncSetAttribute(gemm_tf32_kernel,
                         cudaFuncAttributeMaxDynamicSharedMemorySize,
                         GEMM_SMEM_BYTES);
    cudaFuncSetAttribute(attn_kernel,
                         cudaFuncAttributeMaxDynamicSharedMemorySize,
                         ATTN_SMEM_BYTES);

    // 1) QKV projection + bias (TF32 tensor cores)
    gemm_tf32_kernel<<<dim3(QKV_OUT / BN, T_DIM / BM), 256, GEMM_SMEM_BYTES>>>(
        hidden, w_qkv, b_qkv, qkv_ptr, T_DIM, QKV_OUT, HIDDEN);

    // 2) RoPE on q + k heads
    rope_kernel<<<dim3(T_DIM, N_HEADS + N_KV), 64>>>(positions);

    // 3) Sliding-window GQA flash attention (QK + PV on tensor cores)
    attn_kernel<<<dim3(T_DIM / AQ, N_HEADS), 128, ATTN_SMEM_BYTES>>>();

    // 4) Output projection (TF32 tensor cores)
    gemm_tf32_kernel<<<dim3(HIDDEN / BN, T_DIM / BM), 256, GEMM_SMEM_BYTES>>>(
        attn_ptr, w_o, nullptr, out, T_DIM, HIDDEN, N_HEADS * HEAD_DIM);
}

// round 16
// speedup vs baseline: 4.0405x; 1.0556x over previous
#include <cuda_runtime.h>
#include <math.h>
#include <stdint.h>

// Problem constants
#define T_DIM    4096
#define HIDDEN   2048
#define N_HEADS  16
#define N_KV     4
#define HEAD_DIM 128
#define WINDOW   1024
#define QKV_OUT  3072           // (16 + 2*4) * 128
#define Q_SIZE   2048           // 16*128
#define KV_SIZE  512            // 4*128

// Scratch (no cudaMalloc allowed)
__device__ float g_qkv [(size_t)T_DIM * QKV_OUT];            // 50.3 MB
__device__ float g_attn[(size_t)T_DIM * N_HEADS * HEAD_DIM]; // 33.5 MB (tf32-exact)
__device__ float g_hid [(size_t)T_DIM * HIDDEN];             // 33.5 MB (tf32-exact)
__device__ float g_wqkv[(size_t)HIDDEN * QKV_OUT];           // 25.2 MB (tf32-exact)
__device__ float g_wo  [(size_t)HIDDEN * HIDDEN];            // 16.8 MB (tf32-exact)

__device__ __forceinline__ uint32_t f2tf32(float x) {
    uint32_t u;
    asm("cvt.rna.tf32.f32 %0, %1;" : "=r"(u) : "f"(x));
    return u;
}

__device__ __forceinline__ void mma_tf32(
    float& c0, float& c1, float& c2, float& c3,
    uint32_t a0, uint32_t a1, uint32_t a2, uint32_t a3,
    uint32_t b0, uint32_t b1)
{
    asm("mma.sync.aligned.m16n8k8.row.col.f32.tf32.tf32.f32 "
        "{%0,%1,%2,%3}, {%4,%5,%6,%7}, {%8,%9}, {%0,%1,%2,%3};"
        : "+f"(c0), "+f"(c1), "+f"(c2), "+f"(c3)
        : "r"(a0), "r"(a1), "r"(a2), "r"(a3), "r"(b0), "r"(b1));
}

__device__ __forceinline__ uint4 cvt4(float4 v) {
    return make_uint4(f2tf32(v.x), f2tf32(v.y), f2tf32(v.z), f2tf32(v.w));
}

__device__ __forceinline__ void cp_async16(uint32_t smem_addr, const void* gptr) {
    asm volatile("cp.async.cg.shared.global [%0], [%1], 16;\n"
                 :: "r"(smem_addr), "l"(gptr));
}
#define CP_COMMIT() asm volatile("cp.async.commit_group;\n" ::)

// ---------------------------------------------------------------------------
// Pre-convert: dst = tf32-round(src), vectorized. Makes operands tf32-exact
// so the GEMM mainloop needs no cvt and can cp.async directly.
// ---------------------------------------------------------------------------
__global__ void cvt_tf32_kernel(const float* __restrict__ src,
                                float* __restrict__ dst, int n4)
{
    int i = blockIdx.x * blockDim.x + threadIdx.x;
    int stride = gridDim.x * blockDim.x;
    for (; i < n4; i += stride) {
        float4 v = ((const float4*)src)[i];
        v.x = __uint_as_float(f2tf32(v.x));
        v.y = __uint_as_float(f2tf32(v.y));
        v.z = __uint_as_float(f2tf32(v.z));
        v.w = __uint_as_float(f2tf32(v.w));
        ((float4*)dst)[i] = v;
    }
}

// ---------------------------------------------------------------------------
// TF32 tensor-core GEMM, cp.async 3-stage pipeline. Operands MUST be
// tf32-exact floats (low 13 mantissa bits zero) — raw bits feed mma directly.
// 128x128 block, BK=32, 256 threads (8 warps 2x4), warp tile 64x32.
// A stride 36 (bank 4g+t), B stride 136 (bank 8t+g): conflict-free.
// ---------------------------------------------------------------------------
#define BM 128
#define BN 128
#define BK 32
#define AS_STRIDE 36
#define BS_STRIDE 136
#define STAGE_WORDS (BM * AS_STRIDE + BK * BS_STRIDE)   // 8960
#define NSTAGE 3
#define GEMM_SMEM_BYTES (NSTAGE * STAGE_WORDS * 4)      // 107,520 B

__global__ __launch_bounds__(256, 2) void gemm_tf32_kernel(
    const float* __restrict__ A, const float* __restrict__ B,
    const float* __restrict__ bias, float* __restrict__ C,
    int M, int N, int K)
{
    extern __shared__ uint32_t gsm[];
    const uint32_t smem_base = (uint32_t)__cvta_generic_to_shared(gsm);

    const int tid = threadIdx.x;
    const int m0  = blockIdx.y * BM;
    const int n0  = blockIdx.x * BN;

    const int wid  = tid >> 5;
    const int lane = tid & 31;
    const int wm   = wid >> 2;        // 0..1
    const int wn   = wid & 3;         // 0..3
    const int g    = lane >> 2;       // 0..7
    const int t    = lane & 3;        // 0..3

    float c[4][4][4];
#pragma unroll
    for (int i = 0; i < 4; i++)
#pragma unroll
        for (int j = 0; j < 4; j++)
#pragma unroll
            for (int u = 0; u < 4; u++) c[i][j][u] = 0.f;

    // Loader mapping: A 128x32 (row tid>>1, 16 cols), B 32x128 (row tid>>3, 16 cols)
    const int arow = tid >> 1;
    const int acol = (tid & 1) * 16;
    const int brow = tid >> 3;
    const int bcol = (tid & 7) * 16;

    const uint32_t a_soff = (uint32_t)(arow * AS_STRIDE + acol) * 4;
    const uint32_t b_soff = (uint32_t)(BM * AS_STRIDE + brow * BS_STRIDE + bcol) * 4;

    const float* AgBase = A + (size_t)(m0 + arow) * K + acol;
    const float* BgBase = B + (size_t)brow * N + n0 + bcol;

    const int NI = K / BK;

    // issue stage st covering k-range [k0, k0+BK)
    auto issue = [&](int st, int k0) {
        const uint32_t sb = smem_base + (uint32_t)st * (STAGE_WORDS * 4);
        const float* ag = AgBase + k0;
        const float* bg = BgBase + (size_t)k0 * N;
        cp_async16(sb + a_soff + 0,  ag + 0);
        cp_async16(sb + a_soff + 16, ag + 4);
        cp_async16(sb + a_soff + 32, ag + 8);
        cp_async16(sb + a_soff + 48, ag + 12);
        cp_async16(sb + b_soff + 0,  bg + 0);
        cp_async16(sb + b_soff + 16, bg + 4);
        cp_async16(sb + b_soff + 32, bg + 8);
        cp_async16(sb + b_soff + 48, bg + 12);
    };

    issue(0, 0);      CP_COMMIT();
    issue(1, BK);     CP_COMMIT();

    for (int i = 0; i < NI; i++) {
        if (i + 1 < NI) {
            asm volatile("cp.async.wait_group 1;\n" ::);
        } else {
            asm volatile("cp.async.wait_group 0;\n" ::);
        }
        __syncthreads();    // stage i data published; prior readers of (i+2)%3 done

        if (i + 2 < NI) {
            issue((i + 2) % NSTAGE, (i + 2) * BK);
            CP_COMMIT();
        }

        const int st = i % NSTAGE;
        const uint32_t* Ab = gsm + (size_t)st * STAGE_WORDS;
        const uint32_t* Bb = Ab + BM * AS_STRIDE;

#pragma unroll
        for (int ks = 0; ks < 4; ks++) {
            const int kk = ks * 8;
            uint32_t bf0[4], bf1[4];
#pragma unroll
            for (int nt = 0; nt < 4; nt++) {
                const int col = wn * 32 + nt * 8 + g;
                bf0[nt] = Bb[(kk + t) * BS_STRIDE + col];
                bf1[nt] = Bb[(kk + 4 + t) * BS_STRIDE + col];
            }
#pragma unroll
            for (int mt = 0; mt < 4; mt++) {
                const int r = wm * 64 + mt * 16 + g;
                uint32_t fa0 = Ab[r * AS_STRIDE + kk + t];
                uint32_t fa1 = Ab[(r + 8) * AS_STRIDE + kk + t];
                uint32_t fa2 = Ab[r * AS_STRIDE + kk + t + 4];
                uint32_t fa3 = Ab[(r + 8) * AS_STRIDE + kk + t + 4];
#pragma unroll
                for (int nt = 0; nt < 4; nt++)
                    mma_tf32(c[mt][nt][0], c[mt][nt][1], c[mt][nt][2], c[mt][nt][3],
                             fa0, fa1, fa2, fa3, bf0[nt], bf1[nt]);
            }
        }
    }

    // Epilogue
#pragma unroll
    for (int mt = 0; mt < 4; mt++) {
#pragma unroll
        for (int nt = 0; nt < 4; nt++) {
            const int row0 = m0 + wm * 64 + mt * 16 + g;
            const int row1 = row0 + 8;
            const int col  = n0 + wn * 32 + nt * 8 + 2 * t;
            float bb0 = bias ? bias[col]     : 0.f;
            float bb1 = bias ? bias[col + 1] : 0.f;
            float2 v0 = make_float2(c[mt][nt][0] + bb0, c[mt][nt][1] + bb1);
            float2 v1 = make_float2(c[mt][nt][2] + bb0, c[mt][nt][3] + bb1);
            *(float2*)&C[(size_t)row0 * N + col] = v0;
            *(float2*)&C[(size_t)row1 * N + col] = v1;
        }
    }
}

// ---------------------------------------------------------------------------
// RoPE (unchanged)
// ---------------------------------------------------------------------------
__global__ void rope_kernel(const int* __restrict__ positions)
{
    const int t  = blockIdx.x;
    const int hh = blockIdx.y;
    const int d  = threadIdx.x;

    const size_t base = (size_t)t * QKV_OUT +
        ((hh < N_HEADS) ? hh * HEAD_DIM : Q_SIZE + (hh - N_HEADS) * HEAD_DIM);

    const float pos = (float)positions[t];
    const float inv_freq = powf(100000.0f, -((float)d) * (1.0f / 64.0f));
    float sn, cs;
    sincosf(pos * inv_freq, &sn, &cs);

    const float x1 = g_qkv[base + d];
    const float x2 = g_qkv[base + d + 64];
    g_qkv[base + d]      = x1 * cs - x2 * sn;
    g_qkv[base + d + 64] = x2 * cs + x1 * sn;
}

// ---------------------------------------------------------------------------
// Flash attention: QK^T AND PV on tf32 tensor cores (R8/R14 winner).
// Epilogue writes tf32-exact floats so the out-proj GEMM needs no cvt.
// ---------------------------------------------------------------------------
#define AQ 64
#define AK 64
#define KS_STRIDE 132   // bank 4g+t for QK B-frags: conflict-free
#define VS_STRIDE 136   // bank 8t+g for PV B-frags: conflict-free
#define PS_STRIDE 68    // bank 4g+t for PV A-frags: conflict-free

#define ATTN_SMEM_BYTES ((AK * KS_STRIDE + AK * VS_STRIDE + AQ * PS_STRIDE) * 4)

__global__ __launch_bounds__(128, 2) void attn_kernel()
{
    extern __shared__ uint32_t smraw[];
    uint32_t* Ks = smraw;                       // 64 x 132 tf32 bits
    uint32_t* Vs = Ks + AK * KS_STRIDE;         // 64 x 136 tf32 bits
    uint32_t* Ps = Vs + AK * VS_STRIDE;         // 64 x 68  tf32 bits

    const int tid  = threadIdx.x;
    const int h    = blockIdx.y;
    const int qb   = blockIdx.x * AQ;
    const int kvh  = h >> 2;

    const int warp = tid >> 5;
    const int lane = tid & 31;
    const int g    = lane >> 2;        // 0..7
    const int t    = lane & 3;         // 0..3

    const int i0 = qb + warp * 16 + g;
    const int i1 = i0 + 8;

    // Q fragments in registers: 16 k-steps x 4 regs (tf32)
    uint32_t qa[16][4];
    {
        const float* q0p = &g_qkv[(size_t)i0 * QKV_OUT + h * HEAD_DIM];
        const float* q1p = q0p + (size_t)8 * QKV_OUT;
#pragma unroll
        for (int ks = 0; ks < 16; ks++) {
            qa[ks][0] = f2tf32(q0p[8 * ks + t]);
            qa[ks][1] = f2tf32(q1p[8 * ks + t]);
            qa[ks][2] = f2tf32(q0p[8 * ks + t + 4]);
            qa[ks][3] = f2tf32(q1p[8 * ks + t + 4]);
        }
    }

    // O fragments: 16 n8-tiles over HEAD_DIM, 4 regs each
    float o[16][4];
#pragma unroll
    for (int nt = 0; nt < 16; nt++)
#pragma unroll
        for (int u = 0; u < 4; u++) o[nt][u] = 0.f;

    float m0 = -1e30f, m1 = -1e30f, l0 = 0.f, l1 = 0.f;

    int lo = qb - WINDOW;
    if (lo < 0) lo = 0;
    const float scale = 0.08838834764831845f;

    for (int kt = lo; kt <= qb; kt += AK) {
        __syncthreads();
#pragma unroll
        for (int it = 0; it < 16; it++) {
            int idx = it * 128 + tid;
            int r   = idx >> 5;
            int c4  = idx & 31;
            size_t base = (size_t)(kt + r) * QKV_OUT + Q_SIZE + kvh * HEAD_DIM + c4 * 4;
            float4 kv = *(const float4*)&g_qkv[base];
            float4 vv = *(const float4*)&g_qkv[base + KV_SIZE];
            *(uint4*)&Ks[r * KS_STRIDE + c4 * 4] = cvt4(kv);
            *(uint4*)&Vs[r * VS_STRIDE + c4 * 4] = cvt4(vv);
        }
        __syncthreads();

        // ---- S = Q @ K^T ----
        float s[8][4];
#pragma unroll
        for (int nt = 0; nt < 8; nt++)
#pragma unroll
            for (int u = 0; u < 4; u++) s[nt][u] = 0.f;

#pragma unroll
        for (int ks = 0; ks < 16; ks++) {
#pragma unroll
            for (int nt = 0; nt < 8; nt++) {
                uint32_t b0 = Ks[(8 * nt + g) * KS_STRIDE + 8 * ks + t];
                uint32_t b1 = Ks[(8 * nt + g) * KS_STRIDE + 8 * ks + t + 4];
                mma_tf32(s[nt][0], s[nt][1], s[nt][2], s[nt][3],
                         qa[ks][0], qa[ks][1], qa[ks][2], qa[ks][3], b0, b1);
            }
        }

        // ---- mask + scale + fragment softmax ----
        float rm0 = -INFINITY, rm1 = -INFINITY;
#pragma unroll
        for (int nt = 0; nt < 8; nt++) {
#pragma unroll
            for (int e = 0; e < 2; e++) {
                int j = kt + nt * 8 + 2 * t + e;
                bool v0 = (j <= i0) && (j + WINDOW >= i0);
                bool v1 = (j <= i1) && (j + WINDOW >= i1);
                s[nt][e]     = v0 ? s[nt][e]     * scale : -INFINITY;
                s[nt][2 + e] = v1 ? s[nt][2 + e] * scale : -INFINITY;
                rm0 = fmaxf(rm0, s[nt][e]);
                rm1 = fmaxf(rm1, s[nt][2 + e]);
            }
        }
        rm0 = fmaxf(rm0, __shfl_xor_sync(0xffffffffu, rm0, 1));
        rm0 = fmaxf(rm0, __shfl_xor_sync(0xffffffffu, rm0, 2));
        rm1 = fmaxf(rm1, __shfl_xor_sync(0xffffffffu, rm1, 1));
        rm1 = fmaxf(rm1, __shfl_xor_sync(0xffffffffu, rm1, 2));

        float mn0 = fmaxf(m0, rm0), mn1 = fmaxf(m1, rm1);
        float c0 = __expf(m0 - mn0), c1 = __expf(m1 - mn1);
        float rs0 = 0.f, rs1 = 0.f;
#pragma unroll
        for (int nt = 0; nt < 8; nt++) {
            float p00 = __expf(s[nt][0] - mn0);
            float p01 = __expf(s[nt][1] - mn0);
            float p10 = __expf(s[nt][2] - mn1);
            float p11 = __expf(s[nt][3] - mn1);
            uint32_t* p0 = &Ps[(warp * 16 + g) * PS_STRIDE + nt * 8 + 2 * t];
            uint32_t* p1 = &Ps[(warp * 16 + g + 8) * PS_STRIDE + nt * 8 + 2 * t];
            p0[0] = f2tf32(p00);
            p0[1] = f2tf32(p01);
            p1[0] = f2tf32(p10);
            p1[1] = f2tf32(p11);
            rs0 += p00 + p01;
            rs1 += p10 + p11;
        }
        rs0 += __shfl_xor_sync(0xffffffffu, rs0, 1);
        rs0 += __shfl_xor_sync(0xffffffffu, rs0, 2);
        rs1 += __shfl_xor_sync(0xffffffffu, rs1, 1);
        rs1 += __shfl_xor_sync(0xffffffffu, rs1, 2);

        l0 = l0 * c0 + rs0;
        l1 = l1 * c1 + rs1;
        m0 = mn0;
        m1 = mn1;

#pragma unroll
        for (int nt = 0; nt < 16; nt++) {
            o[nt][0] *= c0;
            o[nt][1] *= c0;
            o[nt][2] *= c1;
            o[nt][3] *= c1;
        }

        __syncwarp();

        // ---- O += P @ V ----
#pragma unroll
        for (int ks = 0; ks < 8; ks++) {
            const int rbase = (warp * 16 + g) * PS_STRIDE + 8 * ks;
            uint32_t a0 = Ps[rbase + t];
            uint32_t a1 = Ps[rbase + 8 * PS_STRIDE + t];
            uint32_t a2 = Ps[rbase + t + 4];
            uint32_t a3 = Ps[rbase + 8 * PS_STRIDE + t + 4];
#pragma unroll
            for (int nt = 0; nt < 16; nt++) {
                uint32_t b0 = Vs[(8 * ks + t) * VS_STRIDE + 8 * nt + g];
                uint32_t b1 = Vs[(8 * ks + t + 4) * VS_STRIDE + 8 * nt + g];
                mma_tf32(o[nt][0], o[nt][1], o[nt][2], o[nt][3],
                         a0, a1, a2, a3, b0, b1);
            }
        }
        __syncwarp();
    }

    // Final normalization + store as tf32-exact floats (out-proj reads raw)
    const float inv0 = 1.f / l0;
    const float inv1 = 1.f / l1;
    float* out0 = &g_attn[(size_t)i0 * (N_HEADS * HEAD_DIM) + h * HEAD_DIM];
    float* out1 = &g_attn[(size_t)i1 * (N_HEADS * HEAD_DIM) + h * HEAD_DIM];
#pragma unroll
    for (int nt = 0; nt < 16; nt++) {
        const int col = nt * 8 + 2 * t;
        *(float2*)&out0[col] = make_float2(__uint_as_float(f2tf32(o[nt][0] * inv0)),
                                           __uint_as_float(f2tf32(o[nt][1] * inv0)));
        *(float2*)&out1[col] = make_float2(__uint_as_float(f2tf32(o[nt][2] * inv1)),
                                           __uint_as_float(f2tf32(o[nt][3] * inv1)));
    }
}

// ---------------------------------------------------------------------------
// Launch
// ---------------------------------------------------------------------------
extern "C" void kernel_launch(void* const* d_in, const int* in_sizes, int n_in,
                              void* d_out, int out_size)
{
    const float* hidden    = (const float*)d_in[0];
    const int*   positions = (const int*)  d_in[1];
    const float* w_qkv     = (const float*)d_in[2];
    const float* b_qkv     = (const float*)d_in[3];
    const float* w_o       = (const float*)d_in[4];
    float*       out       = (float*)d_out;

    float *qkv_ptr, *attn_ptr, *hid_ptr, *wqkv_ptr, *wo_ptr;
    cudaGetSymbolAddress((void**)&qkv_ptr,  g_qkv);
    cudaGetSymbolAddress((void**)&attn_ptr, g_attn);
    cudaGetSymbolAddress((void**)&hid_ptr,  g_hid);
    cudaGetSymbolAddress((void**)&wqkv_ptr, g_wqkv);
    cudaGetSymbolAddress((void**)&wo_ptr,   g_wo);

    cudaFuncSetAttribute(gemm_tf32_kernel,
                         cudaFuncAttributeMaxDynamicSharedMemorySize,
                         GEMM_SMEM_BYTES);
    cudaFuncSetAttribute(attn_kernel,
                         cudaFuncAttributeMaxDynamicSharedMemorySize,
                         ATTN_SMEM_BYTES);

    // 0) Pre-convert operands to tf32-exact floats
    cvt_tf32_kernel<<<1024, 256>>>(hidden, hid_ptr,  (T_DIM * HIDDEN) / 4);
    cvt_tf32_kernel<<<1024, 256>>>(w_qkv,  wqkv_ptr, (HIDDEN * QKV_OUT) / 4);
    cvt_tf32_kernel<<<1024, 256>>>(w_o,    wo_ptr,   (HIDDEN * HIDDEN) / 4);

    // 1) QKV projection + bias (cp.async-pipelined TF32 GEMM)
    gemm_tf32_kernel<<<dim3(QKV_OUT / BN, T_DIM / BM), 256, GEMM_SMEM_BYTES>>>(
        hid_ptr, wqkv_ptr, b_qkv, qkv_ptr, T_DIM, QKV_OUT, HIDDEN);

    // 2) RoPE on q + k heads
    rope_kernel<<<dim3(T_DIM, N_HEADS + N_KV), 64>>>(positions);

    // 3) Sliding-window GQA flash attention (QK + PV on tensor cores)
    attn_kernel<<<dim3(T_DIM / AQ, N_HEADS), 128, ATTN_SMEM_BYTES>>>();

    // 4) Output projection (cp.async-pipelined TF32 GEMM)
    gemm_tf32_kernel<<<dim3(HIDDEN / BN, T_DIM / BM), 256, GEMM_SMEM_BYTES>>>(
        attn_ptr, wo_ptr, nullptr, out, T_DIM, HIDDEN, N_HEADS * HEAD_DIM);
}